// round 12
// baseline (speedup 1.0000x reference)
#include <cuda_runtime.h>
#include <cuda_fp16.h>
#include <math.h>
#include <stdint.h>

// Problem dims (fixed by the dataset)
#define Bsz  8192
#define DIN  1024
#define HH   2048
#define DOUT 1000
#define MT   (Bsz / 128)     // 64 m-tiles -> BN partial chunks

// ---------------- scratch (device globals) ----------------------------------
__device__ __align__(256) __half g_act[(size_t)Bsz * HH];       // fp16 activations
__device__ __align__(256) float  g_logits[Bsz * DOUT];
__device__ __align__(256) __half g_A1[(size_t)Bsz * DIN];
__device__ __align__(256) __half g_A2[(size_t)Bsz * HH];
__device__ __align__(256) __half g_W1[(size_t)HH * DIN];
__device__ __align__(256) __half g_W2[(size_t)HH * HH];
__device__ __align__(256) __half g_W3[(size_t)1024 * HH];       // rows 1000.. zero
__device__ float g_psumf[MT * HH];
__device__ float g_psqf [MT * HH];
__device__ float g_scale[HH], g_shift[HH];                      // fused BN affine

// ---------------- helpers -----------------------------------------------------
__device__ __forceinline__ uint32_t smem_to_u32(const void* p) {
    uint32_t a;
    asm("{ .reg .u64 t; cvta.to.shared.u64 t, %1; cvt.u32.u64 %0, t; }" : "=r"(a) : "l"(p));
    return a;
}
#define SW128(off) ((off) ^ (((off) >> 3) & 0x70))

__device__ __forceinline__ void cp_async16(uint32_t daddr, const void* gptr) {
    asm volatile("cp.async.cg.shared.global [%0], [%1], 16;" :: "r"(daddr), "l"(gptr));
}
__device__ __forceinline__ void cp_commit() { asm volatile("cp.async.commit_group;"); }
template <int N>
__device__ __forceinline__ void cp_wait() { asm volatile("cp.async.wait_group %0;" :: "n"(N)); }

__device__ __forceinline__ void ldm_x4(uint32_t* r, uint32_t addr) {
    asm volatile("ldmatrix.sync.aligned.m8n8.x4.shared.b16 {%0,%1,%2,%3}, [%4];"
                 : "=r"(r[0]), "=r"(r[1]), "=r"(r[2]), "=r"(r[3]) : "r"(addr));
}
__device__ __forceinline__ void mma16816(float* d, const uint32_t* a, const uint32_t* b) {
    asm volatile(
        "mma.sync.aligned.m16n8k16.row.col.f32.f16.f16.f32 "
        "{%0,%1,%2,%3}, {%4,%5,%6,%7}, {%8,%9}, {%0,%1,%2,%3};"
        : "+f"(d[0]), "+f"(d[1]), "+f"(d[2]), "+f"(d[3])
        : "r"(a[0]), "r"(a[1]), "r"(a[2]), "r"(a[3]), "r"(b[0]), "r"(b[1]));
}

// typed pair-store: float -> float2, __half -> half2
__device__ __forceinline__ void store2(float* C, size_t idx, float v0, float v1) {
    *reinterpret_cast<float2*>(&C[idx]) = make_float2(v0, v1);
}
__device__ __forceinline__ void store2(__half* C, size_t idx, float v0, float v1) {
    *reinterpret_cast<__half2*>(&C[idx]) = __floats2half2_rn(v0, v1);
}

// ---------------- single-pass fp16 HMMA GEMM, 2-stage / 3 CTAs per SM --------
// C[M,Nreal] = A[M,K] x B[Npad,K]^T + bias, fp16 in / fp32 accum, CT out.
// CTA tile 128x128, BK=64 fp16. 8 warps = 2(M) x 4(N), warp tile 64x32.
// Double-buffered cp.async; 3 CTAs/SM fill each other's barrier bubbles.
// Epilogue optionally emits per-column BN sum/sumsq partials from fp32 values.
static constexpr int TILE_BYTES = 128 * 128;              // 16 KB (A or B, one stage)
static constexpr int SMEM_TOT   = 4 * TILE_BYTES + 1024;  // 2 stages x (A+B)

template <int NC, bool STATS, typename CT>
__global__ void __launch_bounds__(256, 3)
gemm_mma(const __half* __restrict__ A, const __half* __restrict__ B,
         const float* __restrict__ bias, CT* __restrict__ C,
         int Nreal, int Kreal, float* __restrict__ psum, float* __restrict__ psq) {
    extern __shared__ uint8_t smem_raw[];
    uint32_t sb = smem_to_u32(smem_raw);
    sb = (sb + 1023) & ~1023u;

    const int tid  = threadIdx.x;
    const int wid  = tid >> 5, lane = tid & 31;
    const int m0   = blockIdx.y * 128, n0 = blockIdx.x * 128;
    const int wM   = wid >> 2;          // 0..1 -> 64-row slab
    const int wN   = wid & 3;           // 0..3 -> 32-col slab

    auto prefetch = [&](int c, int st) {
        const int k0 = c * 64;
        const uint32_t baseA = sb + (uint32_t)st * 2 * TILE_BYTES;
        const uint32_t baseB = baseA + TILE_BYTES;
#pragma unroll
        for (int i = 0; i < 4; i++) {
            int slot = tid + i * 256;
            int row = slot >> 3, s16 = slot & 7;
            uint32_t so = SW128((uint32_t)(row * 128 + s16 * 16));
            cp_async16(baseA + so, A + (size_t)(m0 + row) * Kreal + k0 + s16 * 8);
            cp_async16(baseB + so, B + (size_t)(n0 + row) * Kreal + k0 + s16 * 8);
        }
        cp_commit();
    };

    float acc[4][4][4];
#pragma unroll
    for (int i = 0; i < 4; i++)
#pragma unroll
        for (int j = 0; j < 4; j++)
#pragma unroll
            for (int q = 0; q < 4; q++) acc[i][j][q] = 0.f;

    const int aRow = wM * 64 + (lane & 15);
    const int aCol = ((lane >> 4) & 1) * 16;
    const int bRow = wN * 32 + (lane & 7) + ((lane >> 4) & 1) * 8;
    const int bCol = ((lane >> 3) & 1) * 16;

    prefetch(0, 0);

    for (int c = 0; c < NC; c++) {
        cp_wait<0>();
        __syncthreads();
        if (c + 1 < NC) prefetch(c + 1, (c + 1) & 1);

        const uint32_t bufA = sb + (uint32_t)(c & 1) * 2 * TILE_BYTES;
        const uint32_t bufB = bufA + TILE_BYTES;
#pragma unroll
        for (int s = 0; s < 4; s++) {
            uint32_t afr[4][4];
#pragma unroll
            for (int mi = 0; mi < 4; mi++) {
                uint32_t addr = bufA + SW128((uint32_t)((aRow + mi * 16) * 128 + s * 32 + aCol));
                ldm_x4(afr[mi], addr);
            }
            uint32_t bfr[4][2];
#pragma unroll
            for (int nh = 0; nh < 2; nh++) {
                uint32_t r[4];
                uint32_t addr = bufB + SW128((uint32_t)((bRow + nh * 16) * 128 + s * 32 + bCol));
                ldm_x4(r, addr);
                bfr[nh * 2][0] = r[0]; bfr[nh * 2][1] = r[1];
                bfr[nh * 2 + 1][0] = r[2]; bfr[nh * 2 + 1][1] = r[3];
            }
#pragma unroll
            for (int mi = 0; mi < 4; mi++)
#pragma unroll
                for (int ni = 0; ni < 4; ni++)
                    mma16816(acc[mi][ni], afr[mi], bfr[ni]);
        }
        __syncthreads();
    }

    // epilogue: bias + store + optional per-column stats partials
    float s8[8], q8[8];
    if (STATS) {
#pragma unroll
        for (int i = 0; i < 8; i++) { s8[i] = 0.f; q8[i] = 0.f; }
    }
#pragma unroll
    for (int mi = 0; mi < 4; mi++) {
        const int row = m0 + wM * 64 + mi * 16 + (lane >> 2);
#pragma unroll
        for (int ni = 0; ni < 4; ni++) {
            const int col = n0 + wN * 32 + ni * 8 + (lane & 3) * 2;
            if (col < Nreal) {
                const float b0 = bias[col], b1 = bias[col + 1];
                float v00 = acc[mi][ni][0] + b0, v01 = acc[mi][ni][1] + b1;
                float v10 = acc[mi][ni][2] + b0, v11 = acc[mi][ni][3] + b1;
                store2(C, (size_t)row * Nreal + col, v00, v01);
                store2(C, (size_t)(row + 8) * Nreal + col, v10, v11);
                if (STATS) {
                    s8[ni * 2]     += v00 + v10;
                    s8[ni * 2 + 1] += v01 + v11;
                    q8[ni * 2]     += v00 * v00 + v10 * v10;
                    q8[ni * 2 + 1] += v01 * v01 + v11 * v11;
                }
            }
        }
    }

    if (STATS) {
        // reduce over the 8 lanes sharing a column (lane>>2 varies, lane&3 fixed)
#pragma unroll
        for (int o = 16; o >= 4; o >>= 1)
#pragma unroll
            for (int i = 0; i < 8; i++) {
                s8[i] += __shfl_xor_sync(0xffffffffu, s8[i], o);
                q8[i] += __shfl_xor_sync(0xffffffffu, q8[i], o);
            }
        __syncthreads();                  // stage buffers now safe to reuse
        float* sred = reinterpret_cast<float*>(smem_raw);      // [2][128]
        float* qred = sred + 256;                              // [2][128]
        if (lane < 4) {
#pragma unroll
            for (int i = 0; i < 8; i++) {
                int colT = wN * 32 + (i >> 1) * 8 + lane * 2 + (i & 1);
                sred[wM * 128 + colT] = s8[i];
                qred[wM * 128 + colT] = q8[i];
            }
        }
        __syncthreads();
        if (tid < 128) {
            const int mt = blockIdx.y;
            psum[(size_t)mt * Nreal + n0 + tid] = sred[tid] + sred[128 + tid];
            psq [(size_t)mt * Nreal + n0 + tid] = qred[tid] + qred[128 + tid];
        }
    }
}

// ---------------- fp16 conversion (zero-pad rows beyond R) -------------------
__global__ __launch_bounds__(256)
void convert_h(const float* __restrict__ X, __half* __restrict__ Y, int R, int K) {
    const int r = blockIdx.x;
    __half* Yr = Y + (size_t)r * K;
    if (r >= R) {
        __half2 z; z.x = __float2half(0.f); z.y = z.x;
        for (int j = threadIdx.x * 2; j < K; j += 512)
            *reinterpret_cast<__half2*>(&Yr[j]) = z;
        return;
    }
    for (int j = threadIdx.x * 2; j < K; j += 512) {
        float2 v = *reinterpret_cast<const float2*>(&X[(size_t)r * K + j]);
        *reinterpret_cast<__half2*>(&Yr[j]) = __floats2half2_rn(v.x, v.y);
    }
}

// ---------------- BN finalize: partials -> fused scale/shift (double) --------
__global__ void bn_finalize(const float* __restrict__ gm, const float* __restrict__ bt) {
    int j = blockIdx.x * blockDim.x + threadIdx.x;
    if (j >= HH) return;
    double s = 0.0, ss = 0.0;
    for (int c = 0; c < MT; c++) {
        s  += (double)g_psumf[(size_t)c * HH + j];
        ss += (double)g_psqf [(size_t)c * HH + j];
    }
    double mu  = s / (double)Bsz;
    double var = ss / (double)Bsz - mu * mu;
    float rstd = (float)(1.0 / sqrt(var + 1e-5));
    float sc = gm[j] * rstd;
    g_scale[j] = sc;
    g_shift[j] = bt[j] - (float)mu * sc;
}

// ---------------- block reductions -------------------------------------------
__device__ __forceinline__ float block_sum256(float v) {
#pragma unroll
    for (int o = 16; o > 0; o >>= 1) v += __shfl_down_sync(0xffffffffu, v, o);
    __shared__ float sh[9];
    int w = threadIdx.x >> 5, l = threadIdx.x & 31;
    if (l == 0) sh[w] = v;
    __syncthreads();
    if (threadIdx.x == 0) {
        float t = 0.f;
#pragma unroll
        for (int q = 0; q < 8; q++) t += sh[q];
        sh[8] = t;
    }
    __syncthreads();
    return sh[8];
}
__device__ __forceinline__ float block_max256(float v) {
#pragma unroll
    for (int o = 16; o > 0; o >>= 1) v = fmaxf(v, __shfl_down_sync(0xffffffffu, v, o));
    __shared__ float sh[9];
    int w = threadIdx.x >> 5, l = threadIdx.x & 31;
    if (l == 0) sh[w] = v;
    __syncthreads();
    if (threadIdx.x == 0) {
        float t = sh[0];
#pragma unroll
        for (int q = 1; q < 8; q++) t = fmaxf(t, sh[q]);
        sh[8] = t;
    }
    __syncthreads();
    return sh[8];
}

// ---------------- stage 1: BN+relu+e2p+log0 -> fp16 --------------------------
__global__ __launch_bounds__(256)
void rowmap_stage1(const __half* __restrict__ act, __half* __restrict__ out) {
    const int row = blockIdx.x;
    float h[8];
    float ssq = 0.f;
#pragma unroll
    for (int p = 0; p < 4; p++) {
        int j = p * 512 + threadIdx.x * 2;
        __half2 y2 = *reinterpret_cast<const __half2*>(&act[(size_t)row * HH + j]);
        float y0 = __half2float(y2.x), y1 = __half2float(y2.y);
        float v0 = fmaxf(fmaf(g_scale[j], y0, g_shift[j]), 0.f);
        float v1 = fmaxf(fmaf(g_scale[j + 1], y1, g_shift[j + 1]), 0.f);
        h[2 * p] = v0; h[2 * p + 1] = v1;
        ssq += v0 * v0 + v1 * v1;
    }
    float tot = block_sum256(ssq);
    float n = sqrtf(tot);
    float coef = 0.f;
    if (n > 0.f) {
        const float sc = 0.31622776601683794f;
        float th = tanhf(sc * n);
        float s  = 0.9f * th / (sc * n);
        float ny = 0.9f * th / sc;
        float dn = fmaxf(ny, 1e-8f);
        coef = -s * atanhf(sc * dn) / (sc * dn);
    }
    __half* Yr = out + (size_t)row * HH;
#pragma unroll
    for (int p = 0; p < 4; p++) {
        int j = p * 512 + threadIdx.x * 2;
        *reinterpret_cast<__half2*>(&Yr[j]) =
            __floats2half2_rn(coef * h[2 * p], coef * h[2 * p + 1]);
    }
}

// ---------------- stage 2: BN+relu+exp0+p2e -> fp16 --------------------------
__global__ __launch_bounds__(256)
void rowmap_stage2(const __half* __restrict__ act, __half* __restrict__ out) {
    const int row = blockIdx.x;
    float h[8];
    float ssq = 0.f;
#pragma unroll
    for (int p = 0; p < 4; p++) {
        int j = p * 512 + threadIdx.x * 2;
        __half2 y2 = *reinterpret_cast<const __half2*>(&act[(size_t)row * HH + j]);
        float y0 = __half2float(y2.x), y1 = __half2float(y2.y);
        float v0 = fmaxf(fmaf(g_scale[j], y0, g_shift[j]), 0.f);
        float v1 = fmaxf(fmaf(g_scale[j + 1], y1, g_shift[j + 1]), 0.f);
        h[2 * p] = v0; h[2 * p + 1] = v1;
        ssq += v0 * v0 + v1 * v1;
    }
    float tot = block_sum256(ssq);
    float n = sqrtf(tot);
    const float sc = 0.31622776601683794f;
    float vn  = fmaxf(n, 1e-8f);
    float scl = tanhf(sc * vn) / (sc * vn);
    float nn  = scl * n;
    float nnc = fminf(fmaxf(nn, 1e-8f), 1.0f);
    float coef = scl * atanhf(sc * nnc) / (sc * nnc);
    __half* Yr = out + (size_t)row * HH;
#pragma unroll
    for (int p = 0; p < 4; p++) {
        int j = p * 512 + threadIdx.x * 2;
        *reinterpret_cast<__half2*>(&Yr[j]) =
            __floats2half2_rn(coef * h[2 * p], coef * h[2 * p + 1]);
    }
}

// ---------------- log_softmax over 1000 cols ---------------------------------
__global__ __launch_bounds__(256)
void log_softmax_kernel(const float* __restrict__ logits, float* __restrict__ out) {
    const int row = blockIdx.x;
    float x[4];
    float mx = -1e30f;
#pragma unroll
    for (int k = 0; k < 4; k++) {
        int j = k * 256 + threadIdx.x;
        x[k] = (j < DOUT) ? logits[(size_t)row * DOUT + j] : -1e30f;
        mx = fmaxf(mx, x[k]);
    }
    mx = block_max256(mx);
    float se = 0.f;
#pragma unroll
    for (int k = 0; k < 4; k++) {
        int j = k * 256 + threadIdx.x;
        if (j < DOUT) se += expf(x[k] - mx);
    }
    se = block_sum256(se);
    float lse = logf(se);
#pragma unroll
    for (int k = 0; k < 4; k++) {
        int j = k * 256 + threadIdx.x;
        if (j < DOUT) out[(size_t)row * DOUT + j] = x[k] - mx - lse;
    }
}

// ---------------- launcher ----------------------------------------------------
extern "C" void kernel_launch(void* const* d_in, const int* in_sizes, int n_in,
                              void* d_out, int out_size) {
    const float* x   = (const float*)d_in[0];
    const float* W1  = (const float*)d_in[1];
    const float* b1  = (const float*)d_in[2];
    const float* g1  = (const float*)d_in[3];
    const float* be1 = (const float*)d_in[4];
    const float* W2  = (const float*)d_in[5];
    const float* b2  = (const float*)d_in[6];
    const float* g2  = (const float*)d_in[7];
    const float* be2 = (const float*)d_in[8];
    const float* W3  = (const float*)d_in[9];
    const float* b3  = (const float*)d_in[10];
    float* out = (float*)d_out;

    float *logits, *psum, *psq;
    __half *act, *A1, *A2, *Wh1, *Wh2, *Wh3;
    cudaGetSymbolAddress((void**)&act,    g_act);
    cudaGetSymbolAddress((void**)&logits, g_logits);
    cudaGetSymbolAddress((void**)&psum,   g_psumf);
    cudaGetSymbolAddress((void**)&psq,    g_psqf);
    cudaGetSymbolAddress((void**)&A1,     g_A1);
    cudaGetSymbolAddress((void**)&A2,     g_A2);
    cudaGetSymbolAddress((void**)&Wh1,    g_W1);
    cudaGetSymbolAddress((void**)&Wh2,    g_W2);
    cudaGetSymbolAddress((void**)&Wh3,    g_W3);

    cudaFuncSetAttribute((const void*)gemm_mma<16, true,  __half>, cudaFuncAttributeMaxDynamicSharedMemorySize, SMEM_TOT);
    cudaFuncSetAttribute((const void*)gemm_mma<32, true,  __half>, cudaFuncAttributeMaxDynamicSharedMemorySize, SMEM_TOT);
    cudaFuncSetAttribute((const void*)gemm_mma<32, false, float>,  cudaFuncAttributeMaxDynamicSharedMemorySize, SMEM_TOT);

    dim3 blk(256);

    // converts (gemm L1 placed at launch index 3 so the profiler lands on it)
    convert_h<<<HH, blk>>>(W1, Wh1, HH, DIN);
    convert_h<<<Bsz, blk>>>(x, A1, Bsz, DIN);
    convert_h<<<HH, blk>>>(W2, Wh2, HH, HH);

    // Layer 1 (K=1024 -> 16 chunks)
    gemm_mma<16, true, __half><<<dim3(HH / 128, Bsz / 128), blk, SMEM_TOT>>>(
        A1, Wh1, b1, act, HH, DIN, psum, psq);
    bn_finalize<<<8, 256>>>(g1, be1);
    rowmap_stage1<<<Bsz, blk>>>(act, A2);
    convert_h<<<1024, blk>>>(W3, Wh3, DOUT, HH);

    // Layer 2 (K=2048 -> 32 chunks)
    gemm_mma<32, true, __half><<<dim3(HH / 128, Bsz / 128), blk, SMEM_TOT>>>(
        A2, Wh2, b2, act, HH, HH, psum, psq);
    bn_finalize<<<8, 256>>>(g2, be2);
    rowmap_stage2<<<Bsz, blk>>>(act, A2);

    // Layer 3 (K=2048 -> 32 chunks)
    gemm_mma<32, false, float><<<dim3(1024 / 128, Bsz / 128), blk, SMEM_TOT>>>(
        A2, Wh3, b3, logits, DOUT, HH, nullptr, nullptr);
    log_softmax_kernel<<<Bsz, blk>>>(logits, out);
}

// round 13
// speedup vs baseline: 2.4599x; 2.4599x over previous
#include <cuda_runtime.h>
#include <cuda_fp16.h>
#include <math.h>
#include <stdint.h>

// Problem dims (fixed by the dataset)
#define Bsz  8192
#define DIN  1024
#define HH   2048
#define DOUT 1000
#define MT   (Bsz / 128)     // 64 m-tiles -> BN partial chunks

// ---------------- scratch (device globals) ----------------------------------
__device__ __align__(256) __half g_act[(size_t)Bsz * HH];       // fp16 activations
__device__ __align__(256) float  g_logits[Bsz * DOUT];
__device__ __align__(256) __half g_A1[(size_t)Bsz * DIN];
__device__ __align__(256) __half g_A2[(size_t)Bsz * HH];
__device__ __align__(256) __half g_W1[(size_t)HH * DIN];
__device__ __align__(256) __half g_W2[(size_t)HH * HH];
__device__ __align__(256) __half g_W3[(size_t)1024 * HH];       // rows 1000.. zero
__device__ float g_psumf[MT * HH];
__device__ float g_psqf [MT * HH];
__device__ float g_scale[HH], g_shift[HH];                      // fused BN affine

// ---------------- helpers -----------------------------------------------------
__device__ __forceinline__ uint32_t smem_to_u32(const void* p) {
    uint32_t a;
    asm("{ .reg .u64 t; cvta.to.shared.u64 t, %1; cvt.u32.u64 %0, t; }" : "=r"(a) : "l"(p));
    return a;
}
#define SW128(off) ((off) ^ (((off) >> 3) & 0x70))

__device__ __forceinline__ void cp_async16(uint32_t daddr, const void* gptr) {
    asm volatile("cp.async.cg.shared.global [%0], [%1], 16;" :: "r"(daddr), "l"(gptr));
}
__device__ __forceinline__ void cp_commit() { asm volatile("cp.async.commit_group;"); }
template <int N>
__device__ __forceinline__ void cp_wait() { asm volatile("cp.async.wait_group %0;" :: "n"(N)); }

__device__ __forceinline__ void ldm_x4(uint32_t* r, uint32_t addr) {
    asm volatile("ldmatrix.sync.aligned.m8n8.x4.shared.b16 {%0,%1,%2,%3}, [%4];"
                 : "=r"(r[0]), "=r"(r[1]), "=r"(r[2]), "=r"(r[3]) : "r"(addr));
}
__device__ __forceinline__ void mma16816(float* d, const uint32_t* a, const uint32_t* b) {
    asm volatile(
        "mma.sync.aligned.m16n8k16.row.col.f32.f16.f16.f32 "
        "{%0,%1,%2,%3}, {%4,%5,%6,%7}, {%8,%9}, {%0,%1,%2,%3};"
        : "+f"(d[0]), "+f"(d[1]), "+f"(d[2]), "+f"(d[3])
        : "r"(a[0]), "r"(a[1]), "r"(a[2]), "r"(a[3]), "r"(b[0]), "r"(b[1]));
}

// typed pair-store: float -> float2, __half -> half2
__device__ __forceinline__ void store2(float* C, size_t idx, float v0, float v1) {
    *reinterpret_cast<float2*>(&C[idx]) = make_float2(v0, v1);
}
__device__ __forceinline__ void store2(__half* C, size_t idx, float v0, float v1) {
    *reinterpret_cast<__half2*>(&C[idx]) = __floats2half2_rn(v0, v1);
}

// ---------------- single-pass fp16 HMMA GEMM (R7/R11 config) -----------------
// C[M,Nreal] = A[M,K] x B[Npad,K]^T + bias, fp16 in / fp32 accum, CT out.
// CTA tile 128x128, BK=64 fp16. 8 warps = 2(M) x 4(N), warp tile 64x32.
// 3-stage cp.async pipeline, 2 CTAs/SM (128 regs/thread — do NOT raise CTA
// count: 3 CTAs forces 80 regs and spills the accumulators, measured R12).
// Epilogue optionally emits per-column BN sum/sumsq partials from fp32 values.
static constexpr int TILE_BYTES = 128 * 128;              // 16 KB (A or B, one stage)
static constexpr int SMEM_TOT   = 6 * TILE_BYTES + 1024;  // 3 stages x (A+B)

template <int NC, bool STATS, typename CT>
__global__ void __launch_bounds__(256, 2)
gemm_mma(const __half* __restrict__ A, const __half* __restrict__ B,
         const float* __restrict__ bias, CT* __restrict__ C,
         int Nreal, int Kreal, float* __restrict__ psum, float* __restrict__ psq) {
    extern __shared__ uint8_t smem_raw[];
    uint32_t sb = smem_to_u32(smem_raw);
    sb = (sb + 1023) & ~1023u;

    const int tid  = threadIdx.x;
    const int wid  = tid >> 5, lane = tid & 31;
    const int m0   = blockIdx.y * 128, n0 = blockIdx.x * 128;
    const int wM   = wid >> 2;          // 0..1 -> 64-row slab
    const int wN   = wid & 3;           // 0..3 -> 32-col slab

    auto prefetch = [&](int c, int st) {
        const int k0 = c * 64;
        const uint32_t baseA = sb + (uint32_t)st * 2 * TILE_BYTES;
        const uint32_t baseB = baseA + TILE_BYTES;
#pragma unroll
        for (int i = 0; i < 4; i++) {
            int slot = tid + i * 256;
            int row = slot >> 3, s16 = slot & 7;
            uint32_t so = SW128((uint32_t)(row * 128 + s16 * 16));
            cp_async16(baseA + so, A + (size_t)(m0 + row) * Kreal + k0 + s16 * 8);
            cp_async16(baseB + so, B + (size_t)(n0 + row) * Kreal + k0 + s16 * 8);
        }
        cp_commit();
    };

    float acc[4][4][4];
#pragma unroll
    for (int i = 0; i < 4; i++)
#pragma unroll
        for (int j = 0; j < 4; j++)
#pragma unroll
            for (int q = 0; q < 4; q++) acc[i][j][q] = 0.f;

    const int aRow = wM * 64 + (lane & 15);
    const int aCol = ((lane >> 4) & 1) * 16;
    const int bRow = wN * 32 + (lane & 7) + ((lane >> 4) & 1) * 8;
    const int bCol = ((lane >> 3) & 1) * 16;

    prefetch(0, 0);
    prefetch(1, 1);

    int st = 0;
    for (int c = 0; c < NC; c++) {
        if (c + 1 < NC) cp_wait<1>(); else cp_wait<0>();
        __syncthreads();
        if (c + 2 < NC) {
            int st2 = st + 2; if (st2 >= 3) st2 -= 3;
            prefetch(c + 2, st2);
        }

        const uint32_t bufA = sb + (uint32_t)st * 2 * TILE_BYTES;
        const uint32_t bufB = bufA + TILE_BYTES;
#pragma unroll
        for (int s = 0; s < 4; s++) {
            uint32_t afr[4][4];
#pragma unroll
            for (int mi = 0; mi < 4; mi++) {
                uint32_t addr = bufA + SW128((uint32_t)((aRow + mi * 16) * 128 + s * 32 + aCol));
                ldm_x4(afr[mi], addr);
            }
            uint32_t bfr[4][2];
#pragma unroll
            for (int nh = 0; nh < 2; nh++) {
                uint32_t r[4];
                uint32_t addr = bufB + SW128((uint32_t)((bRow + nh * 16) * 128 + s * 32 + bCol));
                ldm_x4(r, addr);
                bfr[nh * 2][0] = r[0]; bfr[nh * 2][1] = r[1];
                bfr[nh * 2 + 1][0] = r[2]; bfr[nh * 2 + 1][1] = r[3];
            }
#pragma unroll
            for (int mi = 0; mi < 4; mi++)
#pragma unroll
                for (int ni = 0; ni < 4; ni++)
                    mma16816(acc[mi][ni], afr[mi], bfr[ni]);
        }
        if (++st == 3) st = 0;
    }

    // epilogue: bias + store + optional per-column stats partials
    float s8[8], q8[8];
    if (STATS) {
#pragma unroll
        for (int i = 0; i < 8; i++) { s8[i] = 0.f; q8[i] = 0.f; }
    }
#pragma unroll
    for (int mi = 0; mi < 4; mi++) {
        const int row = m0 + wM * 64 + mi * 16 + (lane >> 2);
#pragma unroll
        for (int ni = 0; ni < 4; ni++) {
            const int col = n0 + wN * 32 + ni * 8 + (lane & 3) * 2;
            if (col < Nreal) {
                const float b0 = bias[col], b1 = bias[col + 1];
                float v00 = acc[mi][ni][0] + b0, v01 = acc[mi][ni][1] + b1;
                float v10 = acc[mi][ni][2] + b0, v11 = acc[mi][ni][3] + b1;
                store2(C, (size_t)row * Nreal + col, v00, v01);
                store2(C, (size_t)(row + 8) * Nreal + col, v10, v11);
                if (STATS) {
                    s8[ni * 2]     += v00 + v10;
                    s8[ni * 2 + 1] += v01 + v11;
                    q8[ni * 2]     += v00 * v00 + v10 * v10;
                    q8[ni * 2 + 1] += v01 * v01 + v11 * v11;
                }
            }
        }
    }

    if (STATS) {
        // reduce over the 8 lanes sharing a column (lane>>2 varies, lane&3 fixed)
#pragma unroll
        for (int o = 16; o >= 4; o >>= 1)
#pragma unroll
            for (int i = 0; i < 8; i++) {
                s8[i] += __shfl_xor_sync(0xffffffffu, s8[i], o);
                q8[i] += __shfl_xor_sync(0xffffffffu, q8[i], o);
            }
        __syncthreads();                  // stage buffers now safe to reuse
        float* sred = reinterpret_cast<float*>(smem_raw);      // [2][128]
        float* qred = sred + 256;                              // [2][128]
        if (lane < 4) {
#pragma unroll
            for (int i = 0; i < 8; i++) {
                int colT = wN * 32 + (i >> 1) * 8 + lane * 2 + (i & 1);
                sred[wM * 128 + colT] = s8[i];
                qred[wM * 128 + colT] = q8[i];
            }
        }
        __syncthreads();
        if (tid < 128) {
            const int mt = blockIdx.y;
            psum[(size_t)mt * Nreal + n0 + tid] = sred[tid] + sred[128 + tid];
            psq [(size_t)mt * Nreal + n0 + tid] = qred[tid] + qred[128 + tid];
        }
    }
}

// ---------------- fp16 conversion (zero-pad rows beyond R) -------------------
__global__ __launch_bounds__(256)
void convert_h(const float* __restrict__ X, __half* __restrict__ Y, int R, int K) {
    const int r = blockIdx.x;
    __half* Yr = Y + (size_t)r * K;
    if (r >= R) {
        __half2 z; z.x = __float2half(0.f); z.y = z.x;
        for (int j = threadIdx.x * 2; j < K; j += 512)
            *reinterpret_cast<__half2*>(&Yr[j]) = z;
        return;
    }
    for (int j = threadIdx.x * 2; j < K; j += 512) {
        float2 v = *reinterpret_cast<const float2*>(&X[(size_t)r * K + j]);
        *reinterpret_cast<__half2*>(&Yr[j]) = __floats2half2_rn(v.x, v.y);
    }
}

// ---------------- BN finalize: partials -> fused scale/shift (double) --------
__global__ void bn_finalize(const float* __restrict__ gm, const float* __restrict__ bt) {
    int j = blockIdx.x * blockDim.x + threadIdx.x;
    if (j >= HH) return;
    double s = 0.0, ss = 0.0;
    for (int c = 0; c < MT; c++) {
        s  += (double)g_psumf[(size_t)c * HH + j];
        ss += (double)g_psqf [(size_t)c * HH + j];
    }
    double mu  = s / (double)Bsz;
    double var = ss / (double)Bsz - mu * mu;
    float rstd = (float)(1.0 / sqrt(var + 1e-5));
    float sc = gm[j] * rstd;
    g_scale[j] = sc;
    g_shift[j] = bt[j] - (float)mu * sc;
}

// ---------------- block reductions -------------------------------------------
__device__ __forceinline__ float block_sum256(float v) {
#pragma unroll
    for (int o = 16; o > 0; o >>= 1) v += __shfl_down_sync(0xffffffffu, v, o);
    __shared__ float sh[9];
    int w = threadIdx.x >> 5, l = threadIdx.x & 31;
    if (l == 0) sh[w] = v;
    __syncthreads();
    if (threadIdx.x == 0) {
        float t = 0.f;
#pragma unroll
        for (int q = 0; q < 8; q++) t += sh[q];
        sh[8] = t;
    }
    __syncthreads();
    return sh[8];
}
__device__ __forceinline__ float block_max256(float v) {
#pragma unroll
    for (int o = 16; o > 0; o >>= 1) v = fmaxf(v, __shfl_down_sync(0xffffffffu, v, o));
    __shared__ float sh[9];
    int w = threadIdx.x >> 5, l = threadIdx.x & 31;
    if (l == 0) sh[w] = v;
    __syncthreads();
    if (threadIdx.x == 0) {
        float t = sh[0];
#pragma unroll
        for (int q = 1; q < 8; q++) t = fmaxf(t, sh[q]);
        sh[8] = t;
    }
    __syncthreads();
    return sh[8];
}

// ---------------- stage 1: BN+relu+e2p+log0 -> fp16 --------------------------
__global__ __launch_bounds__(256)
void rowmap_stage1(const __half* __restrict__ act, __half* __restrict__ out) {
    const int row = blockIdx.x;
    float h[8];
    float ssq = 0.f;
#pragma unroll
    for (int p = 0; p < 4; p++) {
        int j = p * 512 + threadIdx.x * 2;
        __half2 y2 = *reinterpret_cast<const __half2*>(&act[(size_t)row * HH + j]);
        float y0 = __half2float(y2.x), y1 = __half2float(y2.y);
        float v0 = fmaxf(fmaf(g_scale[j], y0, g_shift[j]), 0.f);
        float v1 = fmaxf(fmaf(g_scale[j + 1], y1, g_shift[j + 1]), 0.f);
        h[2 * p] = v0; h[2 * p + 1] = v1;
        ssq += v0 * v0 + v1 * v1;
    }
    float tot = block_sum256(ssq);
    float n = sqrtf(tot);
    float coef = 0.f;
    if (n > 0.f) {
        const float sc = 0.31622776601683794f;
        float th = tanhf(sc * n);
        float s  = 0.9f * th / (sc * n);
        float ny = 0.9f * th / sc;
        float dn = fmaxf(ny, 1e-8f);
        coef = -s * atanhf(sc * dn) / (sc * dn);
    }
    __half* Yr = out + (size_t)row * HH;
#pragma unroll
    for (int p = 0; p < 4; p++) {
        int j = p * 512 + threadIdx.x * 2;
        *reinterpret_cast<__half2*>(&Yr[j]) =
            __floats2half2_rn(coef * h[2 * p], coef * h[2 * p + 1]);
    }
}

// ---------------- stage 2: BN+relu+exp0+p2e -> fp16 --------------------------
__global__ __launch_bounds__(256)
void rowmap_stage2(const __half* __restrict__ act, __half* __restrict__ out) {
    const int row = blockIdx.x;
    float h[8];
    float ssq = 0.f;
#pragma unroll
    for (int p = 0; p < 4; p++) {
        int j = p * 512 + threadIdx.x * 2;
        __half2 y2 = *reinterpret_cast<const __half2*>(&act[(size_t)row * HH + j]);
        float y0 = __half2float(y2.x), y1 = __half2float(y2.y);
        float v0 = fmaxf(fmaf(g_scale[j], y0, g_shift[j]), 0.f);
        float v1 = fmaxf(fmaf(g_scale[j + 1], y1, g_shift[j + 1]), 0.f);
        h[2 * p] = v0; h[2 * p + 1] = v1;
        ssq += v0 * v0 + v1 * v1;
    }
    float tot = block_sum256(ssq);
    float n = sqrtf(tot);
    const float sc = 0.31622776601683794f;
    float vn  = fmaxf(n, 1e-8f);
    float scl = tanhf(sc * vn) / (sc * vn);
    float nn  = scl * n;
    float nnc = fminf(fmaxf(nn, 1e-8f), 1.0f);
    float coef = scl * atanhf(sc * nnc) / (sc * nnc);
    __half* Yr = out + (size_t)row * HH;
#pragma unroll
    for (int p = 0; p < 4; p++) {
        int j = p * 512 + threadIdx.x * 2;
        *reinterpret_cast<__half2*>(&Yr[j]) =
            __floats2half2_rn(coef * h[2 * p], coef * h[2 * p + 1]);
    }
}

// ---------------- log_softmax over 1000 cols ---------------------------------
__global__ __launch_bounds__(256)
void log_softmax_kernel(const float* __restrict__ logits, float* __restrict__ out) {
    const int row = blockIdx.x;
    float x[4];
    float mx = -1e30f;
#pragma unroll
    for (int k = 0; k < 4; k++) {
        int j = k * 256 + threadIdx.x;
        x[k] = (j < DOUT) ? logits[(size_t)row * DOUT + j] : -1e30f;
        mx = fmaxf(mx, x[k]);
    }
    mx = block_max256(mx);
    float se = 0.f;
#pragma unroll
    for (int k = 0; k < 4; k++) {
        int j = k * 256 + threadIdx.x;
        if (j < DOUT) se += expf(x[k] - mx);
    }
    se = block_sum256(se);
    float lse = logf(se);
#pragma unroll
    for (int k = 0; k < 4; k++) {
        int j = k * 256 + threadIdx.x;
        if (j < DOUT) out[(size_t)row * DOUT + j] = x[k] - mx - lse;
    }
}

// ---------------- launcher ----------------------------------------------------
extern "C" void kernel_launch(void* const* d_in, const int* in_sizes, int n_in,
                              void* d_out, int out_size) {
    const float* x   = (const float*)d_in[0];
    const float* W1  = (const float*)d_in[1];
    const float* b1  = (const float*)d_in[2];
    const float* g1  = (const float*)d_in[3];
    const float* be1 = (const float*)d_in[4];
    const float* W2  = (const float*)d_in[5];
    const float* b2  = (const float*)d_in[6];
    const float* g2  = (const float*)d_in[7];
    const float* be2 = (const float*)d_in[8];
    const float* W3  = (const float*)d_in[9];
    const float* b3  = (const float*)d_in[10];
    float* out = (float*)d_out;

    float *logits, *psum, *psq;
    __half *act, *A1, *A2, *Wh1, *Wh2, *Wh3;
    cudaGetSymbolAddress((void**)&act,    g_act);
    cudaGetSymbolAddress((void**)&logits, g_logits);
    cudaGetSymbolAddress((void**)&psum,   g_psumf);
    cudaGetSymbolAddress((void**)&psq,    g_psqf);
    cudaGetSymbolAddress((void**)&A1,     g_A1);
    cudaGetSymbolAddress((void**)&A2,     g_A2);
    cudaGetSymbolAddress((void**)&Wh1,    g_W1);
    cudaGetSymbolAddress((void**)&Wh2,    g_W2);
    cudaGetSymbolAddress((void**)&Wh3,    g_W3);

    cudaFuncSetAttribute((const void*)gemm_mma<16, true,  __half>, cudaFuncAttributeMaxDynamicSharedMemorySize, SMEM_TOT);
    cudaFuncSetAttribute((const void*)gemm_mma<32, true,  __half>, cudaFuncAttributeMaxDynamicSharedMemorySize, SMEM_TOT);
    cudaFuncSetAttribute((const void*)gemm_mma<32, false, float>,  cudaFuncAttributeMaxDynamicSharedMemorySize, SMEM_TOT);

    dim3 blk(256);

    // converts (gemm L1 placed at launch index 3 so the profiler lands on it)
    convert_h<<<HH, blk>>>(W1, Wh1, HH, DIN);
    convert_h<<<Bsz, blk>>>(x, A1, Bsz, DIN);
    convert_h<<<HH, blk>>>(W2, Wh2, HH, HH);

    // Layer 1 (K=1024 -> 16 chunks)
    gemm_mma<16, true, __half><<<dim3(HH / 128, Bsz / 128), blk, SMEM_TOT>>>(
        A1, Wh1, b1, act, HH, DIN, psum, psq);
    bn_finalize<<<8, 256>>>(g1, be1);
    rowmap_stage1<<<Bsz, blk>>>(act, A2);
    convert_h<<<1024, blk>>>(W3, Wh3, DOUT, HH);

    // Layer 2 (K=2048 -> 32 chunks)
    gemm_mma<32, true, __half><<<dim3(HH / 128, Bsz / 128), blk, SMEM_TOT>>>(
        A2, Wh2, b2, act, HH, HH, psum, psq);
    bn_finalize<<<8, 256>>>(g2, be2);
    rowmap_stage2<<<Bsz, blk>>>(act, A2);

    // Layer 3 (K=2048 -> 32 chunks)
    gemm_mma<32, false, float><<<dim3(1024 / 128, Bsz / 128), blk, SMEM_TOT>>>(
        A2, Wh3, b3, logits, DOUT, HH, nullptr, nullptr);
    log_softmax_kernel<<<Bsz, blk>>>(logits, out);
}

// round 14
// speedup vs baseline: 2.5109x; 1.0207x over previous
#include <cuda_runtime.h>
#include <cuda_fp16.h>
#include <math.h>
#include <stdint.h>

// Problem dims (fixed by the dataset)
#define Bsz  8192
#define DIN  1024
#define HH   2048
#define DOUT 1000
#define MT   (Bsz / 128)     // 64 m-tiles -> BN partial chunks

// ---------------- scratch (device globals) ----------------------------------
__device__ __align__(256) __half g_act[(size_t)Bsz * HH];       // fp16 activations
__device__ __align__(256) float  g_logits[Bsz * DOUT];
__device__ __align__(256) __half g_A1[(size_t)Bsz * DIN];
__device__ __align__(256) __half g_A2[(size_t)Bsz * HH];
__device__ __align__(256) __half g_W1[(size_t)HH * DIN];
__device__ __align__(256) __half g_W2[(size_t)HH * HH];
__device__ __align__(256) __half g_W3[(size_t)1024 * HH];       // rows 1000.. unused (never stored)
__device__ float g_psumf[MT * HH];
__device__ float g_psqf [MT * HH];
__device__ float g_scale[HH], g_shift[HH];                      // fused BN affine

// ---------------- helpers -----------------------------------------------------
__device__ __forceinline__ uint32_t smem_to_u32(const void* p) {
    uint32_t a;
    asm("{ .reg .u64 t; cvta.to.shared.u64 t, %1; cvt.u32.u64 %0, t; }" : "=r"(a) : "l"(p));
    return a;
}
#define SW128(off) ((off) ^ (((off) >> 3) & 0x70))

__device__ __forceinline__ void cp_async16(uint32_t daddr, const void* gptr) {
    asm volatile("cp.async.cg.shared.global [%0], [%1], 16;" :: "r"(daddr), "l"(gptr));
}
__device__ __forceinline__ void cp_commit() { asm volatile("cp.async.commit_group;"); }
template <int N>
__device__ __forceinline__ void cp_wait() { asm volatile("cp.async.wait_group %0;" :: "n"(N)); }

__device__ __forceinline__ void ldm_x4(uint32_t* r, uint32_t addr) {
    asm volatile("ldmatrix.sync.aligned.m8n8.x4.shared.b16 {%0,%1,%2,%3}, [%4];"
                 : "=r"(r[0]), "=r"(r[1]), "=r"(r[2]), "=r"(r[3]) : "r"(addr));
}
__device__ __forceinline__ void mma16816(float* d, const uint32_t* a, const uint32_t* b) {
    asm volatile(
        "mma.sync.aligned.m16n8k16.row.col.f32.f16.f16.f32 "
        "{%0,%1,%2,%3}, {%4,%5,%6,%7}, {%8,%9}, {%0,%1,%2,%3};"
        : "+f"(d[0]), "+f"(d[1]), "+f"(d[2]), "+f"(d[3])
        : "r"(a[0]), "r"(a[1]), "r"(a[2]), "r"(a[3]), "r"(b[0]), "r"(b[1]));
}

// typed pair-store: float -> float2, __half -> half2
__device__ __forceinline__ void store2(float* C, size_t idx, float v0, float v1) {
    *reinterpret_cast<float2*>(&C[idx]) = make_float2(v0, v1);
}
__device__ __forceinline__ void store2(__half* C, size_t idx, float v0, float v1) {
    *reinterpret_cast<__half2*>(&C[idx]) = __floats2half2_rn(v0, v1);
}

// ---------------- single-pass fp16 HMMA GEMM (R7/R11 config) -----------------
// C[M,Nreal] = A[M,K] x B[Npad,K]^T + bias, fp16 in / fp32 accum, CT out.
// CTA tile 128x128, BK=64 fp16. 8 warps = 2(M) x 4(N), warp tile 64x32.
// 3-stage cp.async pipeline, 2 CTAs/SM (128 regs/thread — do NOT raise CTA
// count: 3 CTAs forces 80 regs and spills the accumulators, measured R12;
// do NOT change warp/tile shape: R5/R8 both regressed).
// Epilogue optionally emits per-column BN sum/sumsq partials from fp32 values.
static constexpr int TILE_BYTES = 128 * 128;              // 16 KB (A or B, one stage)
static constexpr int SMEM_TOT   = 6 * TILE_BYTES + 1024;  // 3 stages x (A+B)

template <int NC, bool STATS, typename CT>
__global__ void __launch_bounds__(256, 2)
gemm_mma(const __half* __restrict__ A, const __half* __restrict__ B,
         const float* __restrict__ bias, CT* __restrict__ C,
         int Nreal, int Kreal, float* __restrict__ psum, float* __restrict__ psq) {
    extern __shared__ uint8_t smem_raw[];
    uint32_t sb = smem_to_u32(smem_raw);
    sb = (sb + 1023) & ~1023u;

    const int tid  = threadIdx.x;
    const int wid  = tid >> 5, lane = tid & 31;
    const int m0   = blockIdx.y * 128, n0 = blockIdx.x * 128;
    const int wM   = wid >> 2;          // 0..1 -> 64-row slab
    const int wN   = wid & 3;           // 0..3 -> 32-col slab

    auto prefetch = [&](int c, int st) {
        const int k0 = c * 64;
        const uint32_t baseA = sb + (uint32_t)st * 2 * TILE_BYTES;
        const uint32_t baseB = baseA + TILE_BYTES;
#pragma unroll
        for (int i = 0; i < 4; i++) {
            int slot = tid + i * 256;
            int row = slot >> 3, s16 = slot & 7;
            uint32_t so = SW128((uint32_t)(row * 128 + s16 * 16));
            cp_async16(baseA + so, A + (size_t)(m0 + row) * Kreal + k0 + s16 * 8);
            cp_async16(baseB + so, B + (size_t)(n0 + row) * Kreal + k0 + s16 * 8);
        }
        cp_commit();
    };

    float acc[4][4][4];
#pragma unroll
    for (int i = 0; i < 4; i++)
#pragma unroll
        for (int j = 0; j < 4; j++)
#pragma unroll
            for (int q = 0; q < 4; q++) acc[i][j][q] = 0.f;

    const int aRow = wM * 64 + (lane & 15);
    const int aCol = ((lane >> 4) & 1) * 16;
    const int bRow = wN * 32 + (lane & 7) + ((lane >> 4) & 1) * 8;
    const int bCol = ((lane >> 3) & 1) * 16;

    prefetch(0, 0);
    prefetch(1, 1);

    int st = 0;
    for (int c = 0; c < NC; c++) {
        if (c + 1 < NC) cp_wait<1>(); else cp_wait<0>();
        __syncthreads();
        if (c + 2 < NC) {
            int st2 = st + 2; if (st2 >= 3) st2 -= 3;
            prefetch(c + 2, st2);
        }

        const uint32_t bufA = sb + (uint32_t)st * 2 * TILE_BYTES;
        const uint32_t bufB = bufA + TILE_BYTES;
#pragma unroll
        for (int s = 0; s < 4; s++) {
            uint32_t afr[4][4];
#pragma unroll
            for (int mi = 0; mi < 4; mi++) {
                uint32_t addr = bufA + SW128((uint32_t)((aRow + mi * 16) * 128 + s * 32 + aCol));
                ldm_x4(afr[mi], addr);
            }
            uint32_t bfr[4][2];
#pragma unroll
            for (int nh = 0; nh < 2; nh++) {
                uint32_t r[4];
                uint32_t addr = bufB + SW128((uint32_t)((bRow + nh * 16) * 128 + s * 32 + bCol));
                ldm_x4(r, addr);
                bfr[nh * 2][0] = r[0]; bfr[nh * 2][1] = r[1];
                bfr[nh * 2 + 1][0] = r[2]; bfr[nh * 2 + 1][1] = r[3];
            }
#pragma unroll
            for (int mi = 0; mi < 4; mi++)
#pragma unroll
                for (int ni = 0; ni < 4; ni++)
                    mma16816(acc[mi][ni], afr[mi], bfr[ni]);
        }
        if (++st == 3) st = 0;
    }

    // epilogue: bias + store + optional per-column stats partials
    float s8[8], q8[8];
    if (STATS) {
#pragma unroll
        for (int i = 0; i < 8; i++) { s8[i] = 0.f; q8[i] = 0.f; }
    }
#pragma unroll
    for (int mi = 0; mi < 4; mi++) {
        const int row = m0 + wM * 64 + mi * 16 + (lane >> 2);
#pragma unroll
        for (int ni = 0; ni < 4; ni++) {
            const int col = n0 + wN * 32 + ni * 8 + (lane & 3) * 2;
            if (col < Nreal) {
                const float b0 = bias[col], b1 = bias[col + 1];
                float v00 = acc[mi][ni][0] + b0, v01 = acc[mi][ni][1] + b1;
                float v10 = acc[mi][ni][2] + b0, v11 = acc[mi][ni][3] + b1;
                store2(C, (size_t)row * Nreal + col, v00, v01);
                store2(C, (size_t)(row + 8) * Nreal + col, v10, v11);
                if (STATS) {
                    s8[ni * 2]     += v00 + v10;
                    s8[ni * 2 + 1] += v01 + v11;
                    q8[ni * 2]     += v00 * v00 + v10 * v10;
                    q8[ni * 2 + 1] += v01 * v01 + v11 * v11;
                }
            }
        }
    }

    if (STATS) {
        // reduce over the 8 lanes sharing a column (lane>>2 varies, lane&3 fixed)
#pragma unroll
        for (int o = 16; o >= 4; o >>= 1)
#pragma unroll
            for (int i = 0; i < 8; i++) {
                s8[i] += __shfl_xor_sync(0xffffffffu, s8[i], o);
                q8[i] += __shfl_xor_sync(0xffffffffu, q8[i], o);
            }
        __syncthreads();                  // stage buffers now safe to reuse
        float* sred = reinterpret_cast<float*>(smem_raw);      // [2][128]
        float* qred = sred + 256;                              // [2][128]
        if (lane < 4) {
#pragma unroll
            for (int i = 0; i < 8; i++) {
                int colT = wN * 32 + (i >> 1) * 8 + lane * 2 + (i & 1);
                sred[wM * 128 + colT] = s8[i];
                qred[wM * 128 + colT] = q8[i];
            }
        }
        __syncthreads();
        if (tid < 128) {
            const int mt = blockIdx.y;
            psum[(size_t)mt * Nreal + n0 + tid] = sred[tid] + sred[128 + tid];
            psq [(size_t)mt * Nreal + n0 + tid] = qred[tid] + qred[128 + tid];
        }
    }
}

// ---------------- fused fp32->fp16 conversion of W1 | x | W2 | W3 ------------
// One launch; blockIdx selects region. Each block converts one 1024-col slab.
// Region layout (in 1024-element slabs):
//   W1: HH*DIN/1024      = 2048 slabs
//   x : Bsz*DIN/1024     = 8192 slabs
//   W2: HH*HH/1024       = 4096 slabs
//   W3: DOUT*HH/1024     = 2000 slabs  (ghost rows 1000..1023 never read back)
static constexpr int SL_W1 = HH * DIN / 1024;
static constexpr int SL_X  = Bsz * DIN / 1024;
static constexpr int SL_W2 = HH * HH / 1024;
static constexpr int SL_W3 = DOUT * HH / 1024;
static constexpr int SL_TOT = SL_W1 + SL_X + SL_W2 + SL_W3;

__global__ __launch_bounds__(256)
void convert_all(const float* __restrict__ W1, const float* __restrict__ x,
                 const float* __restrict__ W2, const float* __restrict__ W3) {
    int b = blockIdx.x;
    const float* src;
    __half* dst;
    if (b < SL_W1)                      { src = W1; dst = g_W1; }
    else if ((b -= SL_W1) < SL_X)       { src = x;  dst = g_A1; }
    else if ((b -= SL_X)  < SL_W2)      { src = W2; dst = g_W2; }
    else                                { b -= SL_W2; src = W3; dst = g_W3; }
    const size_t base = (size_t)b * 1024;
#pragma unroll
    for (int t = 0; t < 2; t++) {
        size_t j = base + threadIdx.x * 2 + t * 512;
        float2 v = *reinterpret_cast<const float2*>(&src[j]);
        *reinterpret_cast<__half2*>(&dst[j]) = __floats2half2_rn(v.x, v.y);
    }
}

// ---------------- BN finalize: partials -> fused scale/shift (double) --------
__global__ void bn_finalize(const float* __restrict__ gm, const float* __restrict__ bt) {
    int j = blockIdx.x * blockDim.x + threadIdx.x;
    if (j >= HH) return;
    double s = 0.0, ss = 0.0;
    for (int c = 0; c < MT; c++) {
        s  += (double)g_psumf[(size_t)c * HH + j];
        ss += (double)g_psqf [(size_t)c * HH + j];
    }
    double mu  = s / (double)Bsz;
    double var = ss / (double)Bsz - mu * mu;
    float rstd = (float)(1.0 / sqrt(var + 1e-5));
    float sc = gm[j] * rstd;
    g_scale[j] = sc;
    g_shift[j] = bt[j] - (float)mu * sc;
}

// ---------------- block reductions -------------------------------------------
__device__ __forceinline__ float block_sum256(float v) {
#pragma unroll
    for (int o = 16; o > 0; o >>= 1) v += __shfl_down_sync(0xffffffffu, v, o);
    __shared__ float sh[9];
    int w = threadIdx.x >> 5, l = threadIdx.x & 31;
    if (l == 0) sh[w] = v;
    __syncthreads();
    if (threadIdx.x == 0) {
        float t = 0.f;
#pragma unroll
        for (int q = 0; q < 8; q++) t += sh[q];
        sh[8] = t;
    }
    __syncthreads();
    return sh[8];
}
__device__ __forceinline__ float block_max256(float v) {
#pragma unroll
    for (int o = 16; o > 0; o >>= 1) v = fmaxf(v, __shfl_down_sync(0xffffffffu, v, o));
    __shared__ float sh[9];
    int w = threadIdx.x >> 5, l = threadIdx.x & 31;
    if (l == 0) sh[w] = v;
    __syncthreads();
    if (threadIdx.x == 0) {
        float t = sh[0];
#pragma unroll
        for (int q = 1; q < 8; q++) t = fmaxf(t, sh[q]);
        sh[8] = t;
    }
    __syncthreads();
    return sh[8];
}

// ---------------- stage 1: BN+relu+e2p+log0 -> fp16 --------------------------
__global__ __launch_bounds__(256)
void rowmap_stage1(const __half* __restrict__ act, __half* __restrict__ out) {
    const int row = blockIdx.x;
    float h[8];
    float ssq = 0.f;
#pragma unroll
    for (int p = 0; p < 4; p++) {
        int j = p * 512 + threadIdx.x * 2;
        __half2 y2 = *reinterpret_cast<const __half2*>(&act[(size_t)row * HH + j]);
        float y0 = __half2float(y2.x), y1 = __half2float(y2.y);
        float v0 = fmaxf(fmaf(g_scale[j], y0, g_shift[j]), 0.f);
        float v1 = fmaxf(fmaf(g_scale[j + 1], y1, g_shift[j + 1]), 0.f);
        h[2 * p] = v0; h[2 * p + 1] = v1;
        ssq += v0 * v0 + v1 * v1;
    }
    float tot = block_sum256(ssq);
    float n = sqrtf(tot);
    float coef = 0.f;
    if (n > 0.f) {
        const float sc = 0.31622776601683794f;
        float th = tanhf(sc * n);
        float s  = 0.9f * th / (sc * n);
        float ny = 0.9f * th / sc;
        float dn = fmaxf(ny, 1e-8f);
        coef = -s * atanhf(sc * dn) / (sc * dn);
    }
    __half* Yr = out + (size_t)row * HH;
#pragma unroll
    for (int p = 0; p < 4; p++) {
        int j = p * 512 + threadIdx.x * 2;
        *reinterpret_cast<__half2*>(&Yr[j]) =
            __floats2half2_rn(coef * h[2 * p], coef * h[2 * p + 1]);
    }
}

// ---------------- stage 2: BN+relu+exp0+p2e -> fp16 --------------------------
__global__ __launch_bounds__(256)
void rowmap_stage2(const __half* __restrict__ act, __half* __restrict__ out) {
    const int row = blockIdx.x;
    float h[8];
    float ssq = 0.f;
#pragma unroll
    for (int p = 0; p < 4; p++) {
        int j = p * 512 + threadIdx.x * 2;
        __half2 y2 = *reinterpret_cast<const __half2*>(&act[(size_t)row * HH + j]);
        float y0 = __half2float(y2.x), y1 = __half2float(y2.y);
        float v0 = fmaxf(fmaf(g_scale[j], y0, g_shift[j]), 0.f);
        float v1 = fmaxf(fmaf(g_scale[j + 1], y1, g_shift[j + 1]), 0.f);
        h[2 * p] = v0; h[2 * p + 1] = v1;
        ssq += v0 * v0 + v1 * v1;
    }
    float tot = block_sum256(ssq);
    float n = sqrtf(tot);
    const float sc = 0.31622776601683794f;
    float vn  = fmaxf(n, 1e-8f);
    float scl = tanhf(sc * vn) / (sc * vn);
    float nn  = scl * n;
    float nnc = fminf(fmaxf(nn, 1e-8f), 1.0f);
    float coef = scl * atanhf(sc * nnc) / (sc * nnc);
    __half* Yr = out + (size_t)row * HH;
#pragma unroll
    for (int p = 0; p < 4; p++) {
        int j = p * 512 + threadIdx.x * 2;
        *reinterpret_cast<__half2*>(&Yr[j]) =
            __floats2half2_rn(coef * h[2 * p], coef * h[2 * p + 1]);
    }
}

// ---------------- log_softmax over 1000 cols ---------------------------------
__global__ __launch_bounds__(256)
void log_softmax_kernel(const float* __restrict__ logits, float* __restrict__ out) {
    const int row = blockIdx.x;
    float x[4];
    float mx = -1e30f;
#pragma unroll
    for (int k = 0; k < 4; k++) {
        int j = k * 256 + threadIdx.x;
        x[k] = (j < DOUT) ? logits[(size_t)row * DOUT + j] : -1e30f;
        mx = fmaxf(mx, x[k]);
    }
    mx = block_max256(mx);
    float se = 0.f;
#pragma unroll
    for (int k = 0; k < 4; k++) {
        int j = k * 256 + threadIdx.x;
        if (j < DOUT) se += expf(x[k] - mx);
    }
    se = block_sum256(se);
    float lse = logf(se);
#pragma unroll
    for (int k = 0; k < 4; k++) {
        int j = k * 256 + threadIdx.x;
        if (j < DOUT) out[(size_t)row * DOUT + j] = x[k] - mx - lse;
    }
}

// ---------------- launcher ----------------------------------------------------
extern "C" void kernel_launch(void* const* d_in, const int* in_sizes, int n_in,
                              void* d_out, int out_size) {
    const float* x   = (const float*)d_in[0];
    const float* W1  = (const float*)d_in[1];
    const float* b1  = (const float*)d_in[2];
    const float* g1  = (const float*)d_in[3];
    const float* be1 = (const float*)d_in[4];
    const float* W2  = (const float*)d_in[5];
    const float* b2  = (const float*)d_in[6];
    const float* g2  = (const float*)d_in[7];
    const float* be2 = (const float*)d_in[8];
    const float* W3  = (const float*)d_in[9];
    const float* b3  = (const float*)d_in[10];
    float* out = (float*)d_out;

    float *logits, *psum, *psq;
    __half *act, *A1, *A2, *Wh1, *Wh2, *Wh3;
    cudaGetSymbolAddress((void**)&act,    g_act);
    cudaGetSymbolAddress((void**)&logits, g_logits);
    cudaGetSymbolAddress((void**)&psum,   g_psumf);
    cudaGetSymbolAddress((void**)&psq,    g_psqf);
    cudaGetSymbolAddress((void**)&A1,     g_A1);
    cudaGetSymbolAddress((void**)&A2,     g_A2);
    cudaGetSymbolAddress((void**)&Wh1,    g_W1);
    cudaGetSymbolAddress((void**)&Wh2,    g_W2);
    cudaGetSymbolAddress((void**)&Wh3,    g_W3);

    cudaFuncSetAttribute((const void*)gemm_mma<16, true,  __half>, cudaFuncAttributeMaxDynamicSharedMemorySize, SMEM_TOT);
    cudaFuncSetAttribute((const void*)gemm_mma<32, true,  __half>, cudaFuncAttributeMaxDynamicSharedMemorySize, SMEM_TOT);
    cudaFuncSetAttribute((const void*)gemm_mma<32, false, float>,  cudaFuncAttributeMaxDynamicSharedMemorySize, SMEM_TOT);

    dim3 blk(256);

    // one fused conversion launch (W1 | x | W2 | W3)
    convert_all<<<SL_TOT, blk>>>(W1, x, W2, W3);

    // Layer 1 (K=1024 -> 16 chunks)
    gemm_mma<16, true, __half><<<dim3(HH / 128, Bsz / 128), blk, SMEM_TOT>>>(
        A1, Wh1, b1, act, HH, DIN, psum, psq);
    bn_finalize<<<8, 256>>>(g1, be1);
    rowmap_stage1<<<Bsz, blk>>>(act, A2);

    // Layer 2 (K=2048 -> 32 chunks)
    gemm_mma<32, true, __half><<<dim3(HH / 128, Bsz / 128), blk, SMEM_TOT>>>(
        A2, Wh2, b2, act, HH, HH, psum, psq);
    bn_finalize<<<8, 256>>>(g2, be2);
    rowmap_stage2<<<Bsz, blk>>>(act, A2);

    // Layer 3 (K=2048 -> 32 chunks); cols >= DOUT never stored, so the ghost
    // rows of g_W3 (1000..1023) may hold arbitrary data safely.
    gemm_mma<32, false, float><<<dim3(1024 / 128, Bsz / 128), blk, SMEM_TOT>>>(
        A2, Wh3, b3, logits, DOUT, HH, nullptr, nullptr);
    log_softmax_kernel<<<Bsz, blk>>>(logits, out);
}

// round 15
// speedup vs baseline: 2.5691x; 1.0232x over previous
#include <cuda_runtime.h>
#include <cuda_fp16.h>
#include <math.h>
#include <stdint.h>

// Problem dims (fixed by the dataset)
#define Bsz  8192
#define DIN  1024
#define HH   2048
#define DOUT 1000
#define MT   (Bsz / 128)     // 64 m-tiles -> BN partial chunks

// ---------------- scratch (device globals) ----------------------------------
__device__ __align__(256) __half g_act[(size_t)Bsz * HH];       // fp16 activations
__device__ __align__(256) float  g_logits[Bsz * DOUT];
__device__ __align__(256) __half g_A1[(size_t)Bsz * DIN];
__device__ __align__(256) __half g_A2[(size_t)Bsz * HH];
__device__ __align__(256) __half g_W1[(size_t)HH * DIN];
__device__ __align__(256) __half g_W2[(size_t)HH * HH];
__device__ __align__(256) __half g_W3[(size_t)1024 * HH];       // rows 1000.. unused (never stored)
__device__ float g_psumf[MT * HH];
__device__ float g_psqf [MT * HH];
__device__ float g_scale[HH], g_shift[HH];                      // fused BN affine
__device__ int   g_cnt[16];                                     // per n-block arrival counters (zero-init)

// ---------------- helpers -----------------------------------------------------
__device__ __forceinline__ uint32_t smem_to_u32(const void* p) {
    uint32_t a;
    asm("{ .reg .u64 t; cvta.to.shared.u64 t, %1; cvt.u32.u64 %0, t; }" : "=r"(a) : "l"(p));
    return a;
}
#define SW128(off) ((off) ^ (((off) >> 3) & 0x70))

__device__ __forceinline__ void cp_async16(uint32_t daddr, const void* gptr) {
    asm volatile("cp.async.cg.shared.global [%0], [%1], 16;" :: "r"(daddr), "l"(gptr));
}
__device__ __forceinline__ void cp_commit() { asm volatile("cp.async.commit_group;"); }
template <int N>
__device__ __forceinline__ void cp_wait() { asm volatile("cp.async.wait_group %0;" :: "n"(N)); }

__device__ __forceinline__ void ldm_x4(uint32_t* r, uint32_t addr) {
    asm volatile("ldmatrix.sync.aligned.m8n8.x4.shared.b16 {%0,%1,%2,%3}, [%4];"
                 : "=r"(r[0]), "=r"(r[1]), "=r"(r[2]), "=r"(r[3]) : "r"(addr));
}
__device__ __forceinline__ void mma16816(float* d, const uint32_t* a, const uint32_t* b) {
    asm volatile(
        "mma.sync.aligned.m16n8k16.row.col.f32.f16.f16.f32 "
        "{%0,%1,%2,%3}, {%4,%5,%6,%7}, {%8,%9}, {%0,%1,%2,%3};"
        : "+f"(d[0]), "+f"(d[1]), "+f"(d[2]), "+f"(d[3])
        : "r"(a[0]), "r"(a[1]), "r"(a[2]), "r"(a[3]), "r"(b[0]), "r"(b[1]));
}

// typed pair-store: float -> float2, __half -> half2
__device__ __forceinline__ void store2(float* C, size_t idx, float v0, float v1) {
    *reinterpret_cast<float2*>(&C[idx]) = make_float2(v0, v1);
}
__device__ __forceinline__ void store2(__half* C, size_t idx, float v0, float v1) {
    *reinterpret_cast<__half2*>(&C[idx]) = __floats2half2_rn(v0, v1);
}

// ---------------- single-pass fp16 HMMA GEMM (R7/R11 config) -----------------
// C[M,Nreal] = A[M,K] x B[Npad,K]^T + bias, fp16 in / fp32 accum, CT out.
// CTA tile 128x128, BK=64 fp16. 8 warps = 2(M) x 4(N), warp tile 64x32.
// 3-stage cp.async pipeline, 2 CTAs/SM (128 regs/thread — do NOT raise CTA
// count: 3 CTAs forces 80 regs and spills the accumulators, measured R12;
// do NOT change warp/tile shape: R5/R8 both regressed).
// STATS epilogue: per-column sum/sumsq partials; the LAST CTA per n-block
// (atomic arrival counter) reduces all MT partials in double and writes the
// fused BN scale/shift, then resets its counter (graph-replay safe).
static constexpr int TILE_BYTES = 128 * 128;              // 16 KB (A or B, one stage)
static constexpr int SMEM_TOT   = 6 * TILE_BYTES + 1024;  // 3 stages x (A+B)

template <int NC, bool STATS, typename CT>
__global__ void __launch_bounds__(256, 2)
gemm_mma(const __half* __restrict__ A, const __half* __restrict__ B,
         const float* __restrict__ bias, CT* __restrict__ C,
         int Nreal, int Kreal, float* __restrict__ psum, float* __restrict__ psq,
         const float* __restrict__ gm, const float* __restrict__ bt) {
    extern __shared__ uint8_t smem_raw[];
    uint32_t sb = smem_to_u32(smem_raw);
    sb = (sb + 1023) & ~1023u;

    const int tid  = threadIdx.x;
    const int wid  = tid >> 5, lane = tid & 31;
    const int m0   = blockIdx.y * 128, n0 = blockIdx.x * 128;
    const int wM   = wid >> 2;          // 0..1 -> 64-row slab
    const int wN   = wid & 3;           // 0..3 -> 32-col slab

    auto prefetch = [&](int c, int st) {
        const int k0 = c * 64;
        const uint32_t baseA = sb + (uint32_t)st * 2 * TILE_BYTES;
        const uint32_t baseB = baseA + TILE_BYTES;
#pragma unroll
        for (int i = 0; i < 4; i++) {
            int slot = tid + i * 256;
            int row = slot >> 3, s16 = slot & 7;
            uint32_t so = SW128((uint32_t)(row * 128 + s16 * 16));
            cp_async16(baseA + so, A + (size_t)(m0 + row) * Kreal + k0 + s16 * 8);
            cp_async16(baseB + so, B + (size_t)(n0 + row) * Kreal + k0 + s16 * 8);
        }
        cp_commit();
    };

    float acc[4][4][4];
#pragma unroll
    for (int i = 0; i < 4; i++)
#pragma unroll
        for (int j = 0; j < 4; j++)
#pragma unroll
            for (int q = 0; q < 4; q++) acc[i][j][q] = 0.f;

    const int aRow = wM * 64 + (lane & 15);
    const int aCol = ((lane >> 4) & 1) * 16;
    const int bRow = wN * 32 + (lane & 7) + ((lane >> 4) & 1) * 8;
    const int bCol = ((lane >> 3) & 1) * 16;

    prefetch(0, 0);
    prefetch(1, 1);

    int st = 0;
    for (int c = 0; c < NC; c++) {
        if (c + 1 < NC) cp_wait<1>(); else cp_wait<0>();
        __syncthreads();
        if (c + 2 < NC) {
            int st2 = st + 2; if (st2 >= 3) st2 -= 3;
            prefetch(c + 2, st2);
        }

        const uint32_t bufA = sb + (uint32_t)st * 2 * TILE_BYTES;
        const uint32_t bufB = bufA + TILE_BYTES;
#pragma unroll
        for (int s = 0; s < 4; s++) {
            uint32_t afr[4][4];
#pragma unroll
            for (int mi = 0; mi < 4; mi++) {
                uint32_t addr = bufA + SW128((uint32_t)((aRow + mi * 16) * 128 + s * 32 + aCol));
                ldm_x4(afr[mi], addr);
            }
            uint32_t bfr[4][2];
#pragma unroll
            for (int nh = 0; nh < 2; nh++) {
                uint32_t r[4];
                uint32_t addr = bufB + SW128((uint32_t)((bRow + nh * 16) * 128 + s * 32 + bCol));
                ldm_x4(r, addr);
                bfr[nh * 2][0] = r[0]; bfr[nh * 2][1] = r[1];
                bfr[nh * 2 + 1][0] = r[2]; bfr[nh * 2 + 1][1] = r[3];
            }
#pragma unroll
            for (int mi = 0; mi < 4; mi++)
#pragma unroll
                for (int ni = 0; ni < 4; ni++)
                    mma16816(acc[mi][ni], afr[mi], bfr[ni]);
        }
        if (++st == 3) st = 0;
    }

    // epilogue: bias + store + optional per-column stats partials
    float s8[8], q8[8];
    if (STATS) {
#pragma unroll
        for (int i = 0; i < 8; i++) { s8[i] = 0.f; q8[i] = 0.f; }
    }
#pragma unroll
    for (int mi = 0; mi < 4; mi++) {
        const int row = m0 + wM * 64 + mi * 16 + (lane >> 2);
#pragma unroll
        for (int ni = 0; ni < 4; ni++) {
            const int col = n0 + wN * 32 + ni * 8 + (lane & 3) * 2;
            if (col < Nreal) {
                const float b0 = bias[col], b1 = bias[col + 1];
                float v00 = acc[mi][ni][0] + b0, v01 = acc[mi][ni][1] + b1;
                float v10 = acc[mi][ni][2] + b0, v11 = acc[mi][ni][3] + b1;
                store2(C, (size_t)row * Nreal + col, v00, v01);
                store2(C, (size_t)(row + 8) * Nreal + col, v10, v11);
                if (STATS) {
                    s8[ni * 2]     += v00 + v10;
                    s8[ni * 2 + 1] += v01 + v11;
                    q8[ni * 2]     += v00 * v00 + v10 * v10;
                    q8[ni * 2 + 1] += v01 * v01 + v11 * v11;
                }
            }
        }
    }

    if (STATS) {
        // reduce over the 8 lanes sharing a column (lane>>2 varies, lane&3 fixed)
#pragma unroll
        for (int o = 16; o >= 4; o >>= 1)
#pragma unroll
            for (int i = 0; i < 8; i++) {
                s8[i] += __shfl_xor_sync(0xffffffffu, s8[i], o);
                q8[i] += __shfl_xor_sync(0xffffffffu, q8[i], o);
            }
        __syncthreads();                  // stage buffers now safe to reuse
        float* sred = reinterpret_cast<float*>(smem_raw);      // [2][128]
        float* qred = sred + 256;                              // [2][128]
        if (lane < 4) {
#pragma unroll
            for (int i = 0; i < 8; i++) {
                int colT = wN * 32 + (i >> 1) * 8 + lane * 2 + (i & 1);
                sred[wM * 128 + colT] = s8[i];
                qred[wM * 128 + colT] = q8[i];
            }
        }
        __syncthreads();
        if (tid < 128) {
            const int mt = blockIdx.y;
            psum[(size_t)mt * Nreal + n0 + tid] = sred[tid] + sred[128 + tid];
            psq [(size_t)mt * Nreal + n0 + tid] = qred[tid] + qred[128 + tid];
        }

        // last CTA of this n-block finalizes BN scale/shift (fused bn_finalize)
        __threadfence();
        __shared__ int is_last;
        if (tid == 0) {
            int old = atomicAdd(&g_cnt[blockIdx.x], 1);
            is_last = (old == (int)gridDim.y - 1) ? 1 : 0;
        }
        __syncthreads();
        if (is_last) {
            if (tid < 128) {
                const int j = n0 + tid;
                double s = 0.0, ss = 0.0;
                for (int c = 0; c < (int)gridDim.y; c++) {
                    s  += (double)psum[(size_t)c * Nreal + j];
                    ss += (double)psq [(size_t)c * Nreal + j];
                }
                double mu  = s / (double)Bsz;
                double var = ss / (double)Bsz - mu * mu;
                float rstd = (float)(1.0 / sqrt(var + 1e-5));
                float scv = gm[j] * rstd;
                g_scale[j] = scv;
                g_shift[j] = bt[j] - (float)mu * scv;
            }
            if (tid == 0) g_cnt[blockIdx.x] = 0;   // reset for next launch / replay
        }
    }
}

// ---------------- fused fp32->fp16 conversion of W1 | x | W2 | W3 ------------
// One launch; blockIdx selects region. Each block converts one 1024-elem slab
// with one float4 load + one uint2 (2x half2) store per thread.
static constexpr int SL_W1 = HH * DIN / 1024;
static constexpr int SL_X  = Bsz * DIN / 1024;
static constexpr int SL_W2 = HH * HH / 1024;
static constexpr int SL_W3 = DOUT * HH / 1024;
static constexpr int SL_TOT = SL_W1 + SL_X + SL_W2 + SL_W3;

__global__ __launch_bounds__(256)
void convert_all(const float* __restrict__ W1, const float* __restrict__ x,
                 const float* __restrict__ W2, const float* __restrict__ W3) {
    int b = blockIdx.x;
    const float* src;
    __half* dst;
    if (b < SL_W1)                      { src = W1; dst = g_W1; }
    else if ((b -= SL_W1) < SL_X)       { src = x;  dst = g_A1; }
    else if ((b -= SL_X)  < SL_W2)      { src = W2; dst = g_W2; }
    else                                { b -= SL_W2; src = W3; dst = g_W3; }
    const size_t j = (size_t)b * 1024 + threadIdx.x * 4;
    float4 v = *reinterpret_cast<const float4*>(&src[j]);
    __half2 h0 = __floats2half2_rn(v.x, v.y);
    __half2 h1 = __floats2half2_rn(v.z, v.w);
    uint2 pk;
    pk.x = *reinterpret_cast<uint32_t*>(&h0);
    pk.y = *reinterpret_cast<uint32_t*>(&h1);
    *reinterpret_cast<uint2*>(&dst[j]) = pk;
}

// ---------------- block reductions -------------------------------------------
__device__ __forceinline__ float block_sum256(float v) {
#pragma unroll
    for (int o = 16; o > 0; o >>= 1) v += __shfl_down_sync(0xffffffffu, v, o);
    __shared__ float sh[9];
    int w = threadIdx.x >> 5, l = threadIdx.x & 31;
    if (l == 0) sh[w] = v;
    __syncthreads();
    if (threadIdx.x == 0) {
        float t = 0.f;
#pragma unroll
        for (int q = 0; q < 8; q++) t += sh[q];
        sh[8] = t;
    }
    __syncthreads();
    return sh[8];
}
__device__ __forceinline__ float block_max256(float v) {
#pragma unroll
    for (int o = 16; o > 0; o >>= 1) v = fmaxf(v, __shfl_down_sync(0xffffffffu, v, o));
    __shared__ float sh[9];
    int w = threadIdx.x >> 5, l = threadIdx.x & 31;
    if (l == 0) sh[w] = v;
    __syncthreads();
    if (threadIdx.x == 0) {
        float t = sh[0];
#pragma unroll
        for (int q = 1; q < 8; q++) t = fmaxf(t, sh[q]);
        sh[8] = t;
    }
    __syncthreads();
    return sh[8];
}

// ---------------- stage 1: BN+relu+e2p+log0 -> fp16 --------------------------
__global__ __launch_bounds__(256)
void rowmap_stage1(const __half* __restrict__ act, __half* __restrict__ out) {
    const int row = blockIdx.x;
    float h[8];
    float ssq = 0.f;
#pragma unroll
    for (int p = 0; p < 4; p++) {
        int j = p * 512 + threadIdx.x * 2;
        __half2 y2 = *reinterpret_cast<const __half2*>(&act[(size_t)row * HH + j]);
        float2 sc2 = *reinterpret_cast<const float2*>(&g_scale[j]);
        float2 sh2 = *reinterpret_cast<const float2*>(&g_shift[j]);
        float v0 = fmaxf(fmaf(sc2.x, __half2float(y2.x), sh2.x), 0.f);
        float v1 = fmaxf(fmaf(sc2.y, __half2float(y2.y), sh2.y), 0.f);
        h[2 * p] = v0; h[2 * p + 1] = v1;
        ssq += v0 * v0 + v1 * v1;
    }
    float tot = block_sum256(ssq);
    float n = sqrtf(tot);
    float coef = 0.f;
    if (n > 0.f) {
        const float sc = 0.31622776601683794f;
        float th = tanhf(sc * n);
        float s  = 0.9f * th / (sc * n);
        float ny = 0.9f * th / sc;
        float dn = fmaxf(ny, 1e-8f);
        coef = -s * atanhf(sc * dn) / (sc * dn);
    }
    __half* Yr = out + (size_t)row * HH;
#pragma unroll
    for (int p = 0; p < 4; p++) {
        int j = p * 512 + threadIdx.x * 2;
        *reinterpret_cast<__half2*>(&Yr[j]) =
            __floats2half2_rn(coef * h[2 * p], coef * h[2 * p + 1]);
    }
}

// ---------------- stage 2: BN+relu+exp0+p2e -> fp16 --------------------------
__global__ __launch_bounds__(256)
void rowmap_stage2(const __half* __restrict__ act, __half* __restrict__ out) {
    const int row = blockIdx.x;
    float h[8];
    float ssq = 0.f;
#pragma unroll
    for (int p = 0; p < 4; p++) {
        int j = p * 512 + threadIdx.x * 2;
        __half2 y2 = *reinterpret_cast<const __half2*>(&act[(size_t)row * HH + j]);
        float2 sc2 = *reinterpret_cast<const float2*>(&g_scale[j]);
        float2 sh2 = *reinterpret_cast<const float2*>(&g_shift[j]);
        float v0 = fmaxf(fmaf(sc2.x, __half2float(y2.x), sh2.x), 0.f);
        float v1 = fmaxf(fmaf(sc2.y, __half2float(y2.y), sh2.y), 0.f);
        h[2 * p] = v0; h[2 * p + 1] = v1;
        ssq += v0 * v0 + v1 * v1;
    }
    float tot = block_sum256(ssq);
    float n = sqrtf(tot);
    const float sc = 0.31622776601683794f;
    float vn  = fmaxf(n, 1e-8f);
    float scl = tanhf(sc * vn) / (sc * vn);
    float nn  = scl * n;
    float nnc = fminf(fmaxf(nn, 1e-8f), 1.0f);
    float coef = scl * atanhf(sc * nnc) / (sc * nnc);
    __half* Yr = out + (size_t)row * HH;
#pragma unroll
    for (int p = 0; p < 4; p++) {
        int j = p * 512 + threadIdx.x * 2;
        *reinterpret_cast<__half2*>(&Yr[j]) =
            __floats2half2_rn(coef * h[2 * p], coef * h[2 * p + 1]);
    }
}

// ---------------- log_softmax over 1000 cols ---------------------------------
__global__ __launch_bounds__(256)
void log_softmax_kernel(const float* __restrict__ logits, float* __restrict__ out) {
    const int row = blockIdx.x;
    float x[4];
    float mx = -1e30f;
#pragma unroll
    for (int k = 0; k < 4; k++) {
        int j = k * 256 + threadIdx.x;
        x[k] = (j < DOUT) ? logits[(size_t)row * DOUT + j] : -1e30f;
        mx = fmaxf(mx, x[k]);
    }
    mx = block_max256(mx);
    float se = 0.f;
#pragma unroll
    for (int k = 0; k < 4; k++) {
        int j = k * 256 + threadIdx.x;
        if (j < DOUT) se += expf(x[k] - mx);
    }
    se = block_sum256(se);
    float lse = logf(se);
#pragma unroll
    for (int k = 0; k < 4; k++) {
        int j = k * 256 + threadIdx.x;
        if (j < DOUT) out[(size_t)row * DOUT + j] = x[k] - mx - lse;
    }
}

// ---------------- launcher ----------------------------------------------------
extern "C" void kernel_launch(void* const* d_in, const int* in_sizes, int n_in,
                              void* d_out, int out_size) {
    const float* x   = (const float*)d_in[0];
    const float* W1  = (const float*)d_in[1];
    const float* b1  = (const float*)d_in[2];
    const float* g1  = (const float*)d_in[3];
    const float* be1 = (const float*)d_in[4];
    const float* W2  = (const float*)d_in[5];
    const float* b2  = (const float*)d_in[6];
    const float* g2  = (const float*)d_in[7];
    const float* be2 = (const float*)d_in[8];
    const float* W3  = (const float*)d_in[9];
    const float* b3  = (const float*)d_in[10];
    float* out = (float*)d_out;

    float *logits, *psum, *psq;
    __half *act, *A1, *A2, *Wh1, *Wh2, *Wh3;
    cudaGetSymbolAddress((void**)&act,    g_act);
    cudaGetSymbolAddress((void**)&logits, g_logits);
    cudaGetSymbolAddress((void**)&psum,   g_psumf);
    cudaGetSymbolAddress((void**)&psq,    g_psqf);
    cudaGetSymbolAddress((void**)&A1,     g_A1);
    cudaGetSymbolAddress((void**)&A2,     g_A2);
    cudaGetSymbolAddress((void**)&Wh1,    g_W1);
    cudaGetSymbolAddress((void**)&Wh2,    g_W2);
    cudaGetSymbolAddress((void**)&Wh3,    g_W3);

    cudaFuncSetAttribute((const void*)gemm_mma<16, true,  __half>, cudaFuncAttributeMaxDynamicSharedMemorySize, SMEM_TOT);
    cudaFuncSetAttribute((const void*)gemm_mma<32, true,  __half>, cudaFuncAttributeMaxDynamicSharedMemorySize, SMEM_TOT);
    cudaFuncSetAttribute((const void*)gemm_mma<32, false, float>,  cudaFuncAttributeMaxDynamicSharedMemorySize, SMEM_TOT);

    dim3 blk(256);

    // one fused conversion launch (W1 | x | W2 | W3)
    convert_all<<<SL_TOT, blk>>>(W1, x, W2, W3);

    // Layer 1 (K=1024 -> 16 chunks); BN finalize fused into GEMM epilogue
    gemm_mma<16, true, __half><<<dim3(HH / 128, Bsz / 128), blk, SMEM_TOT>>>(
        A1, Wh1, b1, act, HH, DIN, psum, psq, g1, be1);
    rowmap_stage1<<<Bsz, blk>>>(act, A2);

    // Layer 2 (K=2048 -> 32 chunks)
    gemm_mma<32, true, __half><<<dim3(HH / 128, Bsz / 128), blk, SMEM_TOT>>>(
        A2, Wh2, b2, act, HH, HH, psum, psq, g2, be2);
    rowmap_stage2<<<Bsz, blk>>>(act, A2);

    // Layer 3 (K=2048 -> 32 chunks); cols >= DOUT never stored, so the ghost
    // rows of g_W3 (1000..1023) may hold arbitrary data safely.
    gemm_mma<32, false, float><<<dim3(1024 / 128, Bsz / 128), blk, SMEM_TOT>>>(
        A2, Wh3, b3, logits, DOUT, HH, nullptr, nullptr, nullptr, nullptr);
    log_softmax_kernel<<<Bsz, blk>>>(logits, out);
}

// round 16
// speedup vs baseline: 2.5769x; 1.0030x over previous
#include <cuda_runtime.h>
#include <cuda_fp16.h>
#include <math.h>
#include <stdint.h>

// Problem dims (fixed by the dataset)
#define Bsz  8192
#define DIN  1024
#define HH   2048
#define DOUT 1000
#define LPAD 1024            // padded logits row stride (float4-aligned rows)
#define MT   (Bsz / 128)     // 64 m-tiles -> BN partial chunks

// ---------------- scratch (device globals) ----------------------------------
__device__ __align__(256) __half g_act[(size_t)Bsz * HH];       // fp16 activations
__device__ __align__(256) float  g_logits[(size_t)Bsz * LPAD];  // padded logits
__device__ __align__(256) __half g_A1[(size_t)Bsz * DIN];
__device__ __align__(256) __half g_A2[(size_t)Bsz * HH];
__device__ __align__(256) __half g_W1[(size_t)HH * DIN];
__device__ __align__(256) __half g_W2[(size_t)HH * HH];
__device__ __align__(256) __half g_W3[(size_t)1024 * HH];       // rows 1000.. unused (never stored)
__device__ __align__(256) float g_psumf[MT * HH];
__device__ __align__(256) float g_psqf [MT * HH];
__device__ __align__(256) float g_scale[HH];
__device__ __align__(256) float g_shift[HH];                    // fused BN affine
__device__ int g_cnt[16];                                       // per n-block arrival counters (zero-init)

// ---------------- helpers -----------------------------------------------------
__device__ __forceinline__ uint32_t smem_to_u32(const void* p) {
    uint32_t a;
    asm("{ .reg .u64 t; cvta.to.shared.u64 t, %1; cvt.u32.u64 %0, t; }" : "=r"(a) : "l"(p));
    return a;
}
#define SW128(off) ((off) ^ (((off) >> 3) & 0x70))

__device__ __forceinline__ void cp_async16(uint32_t daddr, const void* gptr) {
    asm volatile("cp.async.cg.shared.global [%0], [%1], 16;" :: "r"(daddr), "l"(gptr));
}
__device__ __forceinline__ void cp_commit() { asm volatile("cp.async.commit_group;"); }
template <int N>
__device__ __forceinline__ void cp_wait() { asm volatile("cp.async.wait_group %0;" :: "n"(N)); }

__device__ __forceinline__ void ldm_x4(uint32_t* r, uint32_t addr) {
    asm volatile("ldmatrix.sync.aligned.m8n8.x4.shared.b16 {%0,%1,%2,%3}, [%4];"
                 : "=r"(r[0]), "=r"(r[1]), "=r"(r[2]), "=r"(r[3]) : "r"(addr));
}
__device__ __forceinline__ void mma16816(float* d, const uint32_t* a, const uint32_t* b) {
    asm volatile(
        "mma.sync.aligned.m16n8k16.row.col.f32.f16.f16.f32 "
        "{%0,%1,%2,%3}, {%4,%5,%6,%7}, {%8,%9}, {%0,%1,%2,%3};"
        : "+f"(d[0]), "+f"(d[1]), "+f"(d[2]), "+f"(d[3])
        : "r"(a[0]), "r"(a[1]), "r"(a[2]), "r"(a[3]), "r"(b[0]), "r"(b[1]));
}

// typed pair-store: float -> float2, __half -> half2
__device__ __forceinline__ void store2(float* C, size_t idx, float v0, float v1) {
    *reinterpret_cast<float2*>(&C[idx]) = make_float2(v0, v1);
}
__device__ __forceinline__ void store2(__half* C, size_t idx, float v0, float v1) {
    *reinterpret_cast<__half2*>(&C[idx]) = __floats2half2_rn(v0, v1);
}

// ---------------- single-pass fp16 HMMA GEMM (R7/R11 config) -----------------
// C[M, .] = A[M,K] x B[Npad,K]^T + bias, fp16 in / fp32 accum, CT out with row
// stride Nstore (cols >= Nreal never stored).
// CTA tile 128x128, BK=64 fp16. 8 warps = 2(M) x 4(N), warp tile 64x32.
// 3-stage cp.async pipeline, 2 CTAs/SM (128 regs/thread — do NOT raise CTA
// count: 3 CTAs forces 80 regs and spills the accumulators, measured R12;
// do NOT change warp/tile shape: R5/R8 both regressed).
// STATS epilogue: per-column sum/sumsq partials; the LAST CTA per n-block
// (atomic arrival counter) reduces all MT partials in double and writes the
// fused BN scale/shift, then resets its counter (graph-replay safe).
static constexpr int TILE_BYTES = 128 * 128;              // 16 KB (A or B, one stage)
static constexpr int SMEM_TOT   = 6 * TILE_BYTES + 1024;  // 3 stages x (A+B)

template <int NC, bool STATS, typename CT>
__global__ void __launch_bounds__(256, 2)
gemm_mma(const __half* __restrict__ A, const __half* __restrict__ B,
         const float* __restrict__ bias, CT* __restrict__ C,
         int Nreal, int Nstore, int Kreal,
         float* __restrict__ psum, float* __restrict__ psq,
         const float* __restrict__ gm, const float* __restrict__ bt) {
    extern __shared__ uint8_t smem_raw[];
    uint32_t sb = smem_to_u32(smem_raw);
    sb = (sb + 1023) & ~1023u;

    const int tid  = threadIdx.x;
    const int wid  = tid >> 5, lane = tid & 31;
    const int m0   = blockIdx.y * 128, n0 = blockIdx.x * 128;
    const int wM   = wid >> 2;          // 0..1 -> 64-row slab
    const int wN   = wid & 3;           // 0..3 -> 32-col slab

    auto prefetch = [&](int c, int st) {
        const int k0 = c * 64;
        const uint32_t baseA = sb + (uint32_t)st * 2 * TILE_BYTES;
        const uint32_t baseB = baseA + TILE_BYTES;
#pragma unroll
        for (int i = 0; i < 4; i++) {
            int slot = tid + i * 256;
            int row = slot >> 3, s16 = slot & 7;
            uint32_t so = SW128((uint32_t)(row * 128 + s16 * 16));
            cp_async16(baseA + so, A + (size_t)(m0 + row) * Kreal + k0 + s16 * 8);
            cp_async16(baseB + so, B + (size_t)(n0 + row) * Kreal + k0 + s16 * 8);
        }
        cp_commit();
    };

    float acc[4][4][4];
#pragma unroll
    for (int i = 0; i < 4; i++)
#pragma unroll
        for (int j = 0; j < 4; j++)
#pragma unroll
            for (int q = 0; q < 4; q++) acc[i][j][q] = 0.f;

    const int aRow = wM * 64 + (lane & 15);
    const int aCol = ((lane >> 4) & 1) * 16;
    const int bRow = wN * 32 + (lane & 7) + ((lane >> 4) & 1) * 8;
    const int bCol = ((lane >> 3) & 1) * 16;

    prefetch(0, 0);
    prefetch(1, 1);

    int st = 0;
    for (int c = 0; c < NC; c++) {
        if (c + 1 < NC) cp_wait<1>(); else cp_wait<0>();
        __syncthreads();
        if (c + 2 < NC) {
            int st2 = st + 2; if (st2 >= 3) st2 -= 3;
            prefetch(c + 2, st2);
        }

        const uint32_t bufA = sb + (uint32_t)st * 2 * TILE_BYTES;
        const uint32_t bufB = bufA + TILE_BYTES;
#pragma unroll
        for (int s = 0; s < 4; s++) {
            uint32_t afr[4][4];
#pragma unroll
            for (int mi = 0; mi < 4; mi++) {
                uint32_t addr = bufA + SW128((uint32_t)((aRow + mi * 16) * 128 + s * 32 + aCol));
                ldm_x4(afr[mi], addr);
            }
            uint32_t bfr[4][2];
#pragma unroll
            for (int nh = 0; nh < 2; nh++) {
                uint32_t r[4];
                uint32_t addr = bufB + SW128((uint32_t)((bRow + nh * 16) * 128 + s * 32 + bCol));
                ldm_x4(r, addr);
                bfr[nh * 2][0] = r[0]; bfr[nh * 2][1] = r[1];
                bfr[nh * 2 + 1][0] = r[2]; bfr[nh * 2 + 1][1] = r[3];
            }
#pragma unroll
            for (int mi = 0; mi < 4; mi++)
#pragma unroll
                for (int ni = 0; ni < 4; ni++)
                    mma16816(acc[mi][ni], afr[mi], bfr[ni]);
        }
        if (++st == 3) st = 0;
    }

    // epilogue: bias + store + optional per-column stats partials
    float s8[8], q8[8];
    if (STATS) {
#pragma unroll
        for (int i = 0; i < 8; i++) { s8[i] = 0.f; q8[i] = 0.f; }
    }
#pragma unroll
    for (int mi = 0; mi < 4; mi++) {
        const int row = m0 + wM * 64 + mi * 16 + (lane >> 2);
#pragma unroll
        for (int ni = 0; ni < 4; ni++) {
            const int col = n0 + wN * 32 + ni * 8 + (lane & 3) * 2;
            if (col < Nreal) {
                const float b0 = bias[col], b1 = bias[col + 1];
                float v00 = acc[mi][ni][0] + b0, v01 = acc[mi][ni][1] + b1;
                float v10 = acc[mi][ni][2] + b0, v11 = acc[mi][ni][3] + b1;
                store2(C, (size_t)row * Nstore + col, v00, v01);
                store2(C, (size_t)(row + 8) * Nstore + col, v10, v11);
                if (STATS) {
                    s8[ni * 2]     += v00 + v10;
                    s8[ni * 2 + 1] += v01 + v11;
                    q8[ni * 2]     += v00 * v00 + v10 * v10;
                    q8[ni * 2 + 1] += v01 * v01 + v11 * v11;
                }
            }
        }
    }

    if (STATS) {
        // reduce over the 8 lanes sharing a column (lane>>2 varies, lane&3 fixed)
#pragma unroll
        for (int o = 16; o >= 4; o >>= 1)
#pragma unroll
            for (int i = 0; i < 8; i++) {
                s8[i] += __shfl_xor_sync(0xffffffffu, s8[i], o);
                q8[i] += __shfl_xor_sync(0xffffffffu, q8[i], o);
            }
        __syncthreads();                  // stage buffers now safe to reuse
        float* sred = reinterpret_cast<float*>(smem_raw);      // [2][128]
        float* qred = sred + 256;                              // [2][128]
        if (lane < 4) {
#pragma unroll
            for (int i = 0; i < 8; i++) {
                int colT = wN * 32 + (i >> 1) * 8 + lane * 2 + (i & 1);
                sred[wM * 128 + colT] = s8[i];
                qred[wM * 128 + colT] = q8[i];
            }
        }
        __syncthreads();
        if (tid < 128) {
            const int mt = blockIdx.y;
            psum[(size_t)mt * Nreal + n0 + tid] = sred[tid] + sred[128 + tid];
            psq [(size_t)mt * Nreal + n0 + tid] = qred[tid] + qred[128 + tid];
        }

        // last CTA of this n-block finalizes BN scale/shift (fused bn_finalize)
        __threadfence();
        __shared__ int is_last;
        if (tid == 0) {
            int old = atomicAdd(&g_cnt[blockIdx.x], 1);
            is_last = (old == (int)gridDim.y - 1) ? 1 : 0;
        }
        __syncthreads();
        if (is_last) {
            if (tid < 128) {
                const int j = n0 + tid;
                double s = 0.0, ss = 0.0;
                for (int c = 0; c < (int)gridDim.y; c++) {
                    s  += (double)psum[(size_t)c * Nreal + j];
                    ss += (double)psq [(size_t)c * Nreal + j];
                }
                double mu  = s / (double)Bsz;
                double var = ss / (double)Bsz - mu * mu;
                float rstd = (float)(1.0 / sqrt(var + 1e-5));
                float scv = gm[j] * rstd;
                g_scale[j] = scv;
                g_shift[j] = bt[j] - (float)mu * scv;
            }
            if (tid == 0) g_cnt[blockIdx.x] = 0;   // reset for next launch / replay
        }
    }
}

// ---------------- fused fp32->fp16 conversion of W1 | x | W2 | W3 ------------
static constexpr int SL_W1 = HH * DIN / 1024;
static constexpr int SL_X  = Bsz * DIN / 1024;
static constexpr int SL_W2 = HH * HH / 1024;
static constexpr int SL_W3 = DOUT * HH / 1024;
static constexpr int SL_TOT = SL_W1 + SL_X + SL_W2 + SL_W3;

__global__ __launch_bounds__(256)
void convert_all(const float* __restrict__ W1, const float* __restrict__ x,
                 const float* __restrict__ W2, const float* __restrict__ W3) {
    int b = blockIdx.x;
    const float* src;
    __half* dst;
    if (b < SL_W1)                      { src = W1; dst = g_W1; }
    else if ((b -= SL_W1) < SL_X)       { src = x;  dst = g_A1; }
    else if ((b -= SL_X)  < SL_W2)      { src = W2; dst = g_W2; }
    else                                { b -= SL_W2; src = W3; dst = g_W3; }
    const size_t j = (size_t)b * 1024 + threadIdx.x * 4;
    float4 v = *reinterpret_cast<const float4*>(&src[j]);
    __half2 h0 = __floats2half2_rn(v.x, v.y);
    __half2 h1 = __floats2half2_rn(v.z, v.w);
    uint2 pk;
    pk.x = *reinterpret_cast<uint32_t*>(&h0);
    pk.y = *reinterpret_cast<uint32_t*>(&h1);
    *reinterpret_cast<uint2*>(&dst[j]) = pk;
}

// ---------------- block reductions -------------------------------------------
__device__ __forceinline__ float block_sum256(float v) {
#pragma unroll
    for (int o = 16; o > 0; o >>= 1) v += __shfl_down_sync(0xffffffffu, v, o);
    __shared__ float sh[9];
    int w = threadIdx.x >> 5, l = threadIdx.x & 31;
    if (l == 0) sh[w] = v;
    __syncthreads();
    if (threadIdx.x == 0) {
        float t = 0.f;
#pragma unroll
        for (int q = 0; q < 8; q++) t += sh[q];
        sh[8] = t;
    }
    __syncthreads();
    return sh[8];
}
__device__ __forceinline__ float block_max256(float v) {
#pragma unroll
    for (int o = 16; o > 0; o >>= 1) v = fmaxf(v, __shfl_down_sync(0xffffffffu, v, o));
    __shared__ float sh[9];
    int w = threadIdx.x >> 5, l = threadIdx.x & 31;
    if (l == 0) sh[w] = v;
    __syncthreads();
    if (threadIdx.x == 0) {
        float t = sh[0];
#pragma unroll
        for (int q = 1; q < 8; q++) t = fmaxf(t, sh[q]);
        sh[8] = t;
    }
    __syncthreads();
    return sh[8];
}

// ---------------- rowmap core: 4-wide BN+relu, returns values + ssq ----------
__device__ __forceinline__ float rowmap_bn4(const __half* __restrict__ act,
                                            int row, float* h) {
    float ssq = 0.f;
#pragma unroll
    for (int p = 0; p < 2; p++) {
        int j = p * 1024 + threadIdx.x * 4;
        uint2 a = *reinterpret_cast<const uint2*>(&act[(size_t)row * HH + j]);
        __half2 y01 = *reinterpret_cast<__half2*>(&a.x);
        __half2 y23 = *reinterpret_cast<__half2*>(&a.y);
        float4 sc = *reinterpret_cast<const float4*>(&g_scale[j]);
        float4 sh = *reinterpret_cast<const float4*>(&g_shift[j]);
        float v0 = fmaxf(fmaf(sc.x, __half2float(y01.x), sh.x), 0.f);
        float v1 = fmaxf(fmaf(sc.y, __half2float(y01.y), sh.y), 0.f);
        float v2 = fmaxf(fmaf(sc.z, __half2float(y23.x), sh.z), 0.f);
        float v3 = fmaxf(fmaf(sc.w, __half2float(y23.y), sh.w), 0.f);
        h[4 * p] = v0; h[4 * p + 1] = v1; h[4 * p + 2] = v2; h[4 * p + 3] = v3;
        ssq += v0 * v0 + v1 * v1 + v2 * v2 + v3 * v3;
    }
    return ssq;
}

__device__ __forceinline__ void rowmap_store4(__half* __restrict__ out,
                                              int row, const float* h, float coef) {
#pragma unroll
    for (int p = 0; p < 2; p++) {
        int j = p * 1024 + threadIdx.x * 4;
        __half2 h0 = __floats2half2_rn(coef * h[4 * p],     coef * h[4 * p + 1]);
        __half2 h1 = __floats2half2_rn(coef * h[4 * p + 2], coef * h[4 * p + 3]);
        uint2 pk;
        pk.x = *reinterpret_cast<uint32_t*>(&h0);
        pk.y = *reinterpret_cast<uint32_t*>(&h1);
        *reinterpret_cast<uint2*>(&out[(size_t)row * HH + j]) = pk;
    }
}

// ---------------- stage 1: BN+relu+e2p+log0 -> fp16 --------------------------
__global__ __launch_bounds__(256)
void rowmap_stage1(const __half* __restrict__ act, __half* __restrict__ out) {
    const int row = blockIdx.x;
    float h[8];
    float ssq = rowmap_bn4(act, row, h);
    float tot = block_sum256(ssq);
    float n = sqrtf(tot);
    float coef = 0.f;
    if (n > 0.f) {
        const float sc = 0.31622776601683794f;
        float th = tanhf(sc * n);
        float s  = 0.9f * th / (sc * n);
        float ny = 0.9f * th / sc;
        float dn = fmaxf(ny, 1e-8f);
        coef = -s * atanhf(sc * dn) / (sc * dn);
    }
    rowmap_store4(out, row, h, coef);
}

// ---------------- stage 2: BN+relu+exp0+p2e -> fp16 --------------------------
__global__ __launch_bounds__(256)
void rowmap_stage2(const __half* __restrict__ act, __half* __restrict__ out) {
    const int row = blockIdx.x;
    float h[8];
    float ssq = rowmap_bn4(act, row, h);
    float tot = block_sum256(ssq);
    float n = sqrtf(tot);
    const float sc = 0.31622776601683794f;
    float vn  = fmaxf(n, 1e-8f);
    float scl = tanhf(sc * vn) / (sc * vn);
    float nn  = scl * n;
    float nnc = fminf(fmaxf(nn, 1e-8f), 1.0f);
    float coef = scl * atanhf(sc * nnc) / (sc * nnc);
    rowmap_store4(out, row, h, coef);
}

// ---------------- log_softmax: padded 1024-stride input, 1000-col output -----
__global__ __launch_bounds__(256)
void log_softmax_kernel(const float* __restrict__ logits, float* __restrict__ out) {
    const int row = blockIdx.x;
    const int j = threadIdx.x * 4;
    float4 v = *reinterpret_cast<const float4*>(&logits[(size_t)row * LPAD + j]);
    float x0 = (j     < DOUT) ? v.x : -1e30f;
    float x1 = (j + 1 < DOUT) ? v.y : -1e30f;
    float x2 = (j + 2 < DOUT) ? v.z : -1e30f;
    float x3 = (j + 3 < DOUT) ? v.w : -1e30f;
    float mx = block_max256(fmaxf(fmaxf(x0, x1), fmaxf(x2, x3)));
    float se = 0.f;
    if (j     < DOUT) se += expf(x0 - mx);
    if (j + 1 < DOUT) se += expf(x1 - mx);
    if (j + 2 < DOUT) se += expf(x2 - mx);
    if (j + 3 < DOUT) se += expf(x3 - mx);
    se = block_sum256(se);
    float lse = logf(se) + mx;
    if (j + 3 < DOUT) {
        store2(out, (size_t)row * DOUT + j,     x0 - lse, x1 - lse);
        store2(out, (size_t)row * DOUT + j + 2, x2 - lse, x3 - lse);
    }
}

// ---------------- launcher ----------------------------------------------------
extern "C" void kernel_launch(void* const* d_in, const int* in_sizes, int n_in,
                              void* d_out, int out_size) {
    const float* x   = (const float*)d_in[0];
    const float* W1  = (const float*)d_in[1];
    const float* b1  = (const float*)d_in[2];
    const float* g1  = (const float*)d_in[3];
    const float* be1 = (const float*)d_in[4];
    const float* W2  = (const float*)d_in[5];
    const float* b2  = (const float*)d_in[6];
    const float* g2  = (const float*)d_in[7];
    const float* be2 = (const float*)d_in[8];
    const float* W3  = (const float*)d_in[9];
    const float* b3  = (const float*)d_in[10];
    float* out = (float*)d_out;

    float *logits, *psum, *psq;
    __half *act, *A1, *A2, *Wh1, *Wh2, *Wh3;
    cudaGetSymbolAddress((void**)&act,    g_act);
    cudaGetSymbolAddress((void**)&logits, g_logits);
    cudaGetSymbolAddress((void**)&psum,   g_psumf);
    cudaGetSymbolAddress((void**)&psq,    g_psqf);
    cudaGetSymbolAddress((void**)&A1,     g_A1);
    cudaGetSymbolAddress((void**)&A2,     g_A2);
    cudaGetSymbolAddress((void**)&Wh1,    g_W1);
    cudaGetSymbolAddress((void**)&Wh2,    g_W2);
    cudaGetSymbolAddress((void**)&Wh3,    g_W3);

    cudaFuncSetAttribute((const void*)gemm_mma<16, true,  __half>, cudaFuncAttributeMaxDynamicSharedMemorySize, SMEM_TOT);
    cudaFuncSetAttribute((const void*)gemm_mma<32, true,  __half>, cudaFuncAttributeMaxDynamicSharedMemorySize, SMEM_TOT);
    cudaFuncSetAttribute((const void*)gemm_mma<32, false, float>,  cudaFuncAttributeMaxDynamicSharedMemorySize, SMEM_TOT);

    dim3 blk(256);

    // one fused conversion launch (W1 | x | W2 | W3)
    convert_all<<<SL_TOT, blk>>>(W1, x, W2, W3);

    // Layer 1 (K=1024 -> 16 chunks); BN finalize fused into GEMM epilogue
    gemm_mma<16, true, __half><<<dim3(HH / 128, Bsz / 128), blk, SMEM_TOT>>>(
        A1, Wh1, b1, act, HH, HH, DIN, psum, psq, g1, be1);
    rowmap_stage1<<<Bsz, blk>>>(act, A2);

    // Layer 2 (K=2048 -> 32 chunks)
    gemm_mma<32, true, __half><<<dim3(HH / 128, Bsz / 128), blk, SMEM_TOT>>>(
        A2, Wh2, b2, act, HH, HH, HH, psum, psq, g2, be2);
    rowmap_stage2<<<Bsz, blk>>>(act, A2);

    // Layer 3 (K=2048 -> 32 chunks); logits stored with padded stride 1024 so
    // log_softmax rows are float4-aligned; cols >= DOUT never stored.
    gemm_mma<32, false, float><<<dim3(1024 / 128, Bsz / 128), blk, SMEM_TOT>>>(
        A2, Wh3, b3, logits, DOUT, LPAD, HH, nullptr, nullptr, nullptr, nullptr);
    log_softmax_kernel<<<Bsz, blk>>>(logits, out);
}